// round 2
// baseline (speedup 1.0000x reference)
#include <cuda_runtime.h>
#include <math.h>
#include <stdint.h>

// ---------------------------------------------------------------------------
// Problem constants
// ---------------------------------------------------------------------------
#define BATCH   1024
#define NSEQ    128
#define FEAT    128
#define TIME    128
#define DMODEL  256           // FEAT + TIME
#define NHEAD   2
#define DK      128           // DMODEL / NHEAD
#define ROWS    (BATCH*NSEQ)  // 131072

static const float LN_EPS    = 1e-5f;
static const float INV_SCALE = 0.08838834764831845f; // 1/sqrt(128)

// ---------------------------------------------------------------------------
// Scratch (device globals -- no allocation allowed).
// 5 big buffers, aliased across kernel boundaries only:
//   U1: qh   -> sa(post-LN)
//   U2: kh   -> h1(MLP hidden)
//   U3: vh   -> k2(CA key/value input)
//   U4: ao   -> ckh
//   U5: tmp  -> cvh
// ---------------------------------------------------------------------------
__device__ float g_U1[ROWS*DMODEL];
__device__ float g_U2[ROWS*DMODEL];
__device__ float g_U3[ROWS*DMODEL];
__device__ float g_U4[ROWS*DMODEL];
__device__ float g_U5[ROWS*DMODEL];
__device__ float g_cq [BATCH*DMODEL];
__device__ float g_cao[BATCH*DMODEL];
__device__ float g_cln[BATCH*DMODEL];

__device__ int g_mask_mode;  // 0/1 = 32-bit words, 2 = bytes

// ---------------------------------------------------------------------------
// Mask dtype detection: scan first 131072 bytes (safe for every encoding).
//   int32 bool:  words in {0,1}
//   float32:     words in {0, 0x3F800000}
//   bytes:       anything else (packed 0/1 bytes)
// ---------------------------------------------------------------------------
__global__ void detect_mask_kernel(const void* m) {
    __shared__ int bad_int, bad_flt;
    if (threadIdx.x == 0) { bad_int = 0; bad_flt = 0; }
    __syncthreads();
    const unsigned int* w = (const unsigned int*)m;
    int li = 0, lf = 0;
    for (int i = threadIdx.x; i < 32768; i += blockDim.x) {
        unsigned int v = w[i];
        if (v != 0u && v != 1u)           li = 1;
        if (v != 0u && v != 0x3F800000u)  lf = 1;
    }
    if (li) atomicOr(&bad_int, 1);
    if (lf) atomicOr(&bad_flt, 1);
    __syncthreads();
    if (threadIdx.x == 0)
        g_mask_mode = (!bad_int) ? 0 : ((!bad_flt) ? 1 : 2);
}

__device__ __forceinline__ bool is_masked(const void* m, int i) {
    if (g_mask_mode == 2) return ((const unsigned char*)m)[i] != 0;
    return ((const unsigned int*)m)[i] != 0u;  // int32 bool and float32 both
}

// ---------------------------------------------------------------------------
// Generic fp32 SGEMM: C[M,N] = [A0 | A1] @ Bw (+bias)(+relu)
//   A row-gathered concat: col < W0 -> A0, else A1. Bw row-major (K x N).
//   Tile 128x128x8 double-buffered, 256 threads, 8x8 microtile.
//   grid = (N/128, M/128). K and W0/W1 multiples of 8 (here 128/256/384).
// ---------------------------------------------------------------------------
template<int EPI>   // 0 none, 1 +bias, 2 +bias+relu
__launch_bounds__(256)
__global__ void gemm128_kernel(const float* __restrict__ A0, int W0,
                               const float* __restrict__ A1, int W1,
                               const float* __restrict__ Bw,
                               const float* __restrict__ bias,
                               float* __restrict__ C, int N) {
    const int K  = W0 + W1;
    __shared__ float As[2][8][128];
    __shared__ float Bs[2][8][128];
    const int m0 = blockIdx.y * 128;
    const int n0 = blockIdx.x * 128;
    const int tid = threadIdx.x;
    const int tx = tid & 15, ty = tid >> 4;

    // per-thread load coords
    const int a_r = (tid * 4) >> 3;        // row within 128
    const int a_c = (tid * 4) & 7;         // k within 8 (0 or 4)
    const int b_k = (tid * 4) >> 7;        // k within 8
    const int b_n = (tid * 4) & 127;       // n within 128

    float acc[8][8];
#pragma unroll
    for (int i = 0; i < 8; i++)
#pragma unroll
        for (int j = 0; j < 8; j++) acc[i][j] = 0.f;

    // preload tile 0 into buffer 0
    {
        int gc = a_c;
        float4 va = (gc < W0)
            ? *(const float4*)&A0[(size_t)(m0 + a_r) * W0 + gc]
            : *(const float4*)&A1[(size_t)(m0 + a_r) * W1 + (gc - W0)];
        As[0][a_c+0][a_r] = va.x; As[0][a_c+1][a_r] = va.y;
        As[0][a_c+2][a_r] = va.z; As[0][a_c+3][a_r] = va.w;
        float4 vb = *(const float4*)&Bw[(size_t)b_k * N + n0 + b_n];
        *(float4*)&Bs[0][b_k][b_n] = vb;
    }
    __syncthreads();

    int p = 0;
    for (int k0 = 0; k0 < K; k0 += 8, p ^= 1) {
        float4 va, vb;
        const bool has_next = (k0 + 8 < K);
        if (has_next) {                         // issue next-tile LDGs early
            int gc = k0 + 8 + a_c;
            va = (gc < W0)
                ? *(const float4*)&A0[(size_t)(m0 + a_r) * W0 + gc]
                : *(const float4*)&A1[(size_t)(m0 + a_r) * W1 + (gc - W0)];
            vb = *(const float4*)&Bw[(size_t)(k0 + 8 + b_k) * N + n0 + b_n];
        }
#pragma unroll
        for (int kk = 0; kk < 8; kk++) {
            float a[8], bb[8];
            *(float4*)&a[0]  = *(const float4*)&As[p][kk][ty*8];
            *(float4*)&a[4]  = *(const float4*)&As[p][kk][ty*8+4];
            *(float4*)&bb[0] = *(const float4*)&Bs[p][kk][tx*8];
            *(float4*)&bb[4] = *(const float4*)&Bs[p][kk][tx*8+4];
#pragma unroll
            for (int i = 0; i < 8; i++)
#pragma unroll
                for (int j = 0; j < 8; j++)
                    acc[i][j] = fmaf(a[i], bb[j], acc[i][j]);
        }
        if (has_next) {
            As[p^1][a_c+0][a_r] = va.x; As[p^1][a_c+1][a_r] = va.y;
            As[p^1][a_c+2][a_r] = va.z; As[p^1][a_c+3][a_r] = va.w;
            *(float4*)&Bs[p^1][b_k][b_n] = vb;
        }
        __syncthreads();
    }

#pragma unroll
    for (int i = 0; i < 8; i++) {
        int row = m0 + ty*8 + i;
#pragma unroll
        for (int j = 0; j < 8; j++) {
            int col = n0 + tx*8 + j;
            float v = acc[i][j];
            if (EPI >= 1) v += bias[col];
            if (EPI == 2) v = fmaxf(v, 0.f);
            C[(size_t)row * N + col] = v;
        }
    }
}

// ---------------------------------------------------------------------------
// Self-attention, one CTA per (b, h). Everything stays in SMEM.
// ---------------------------------------------------------------------------
#define TP 132
#define SP 129
#define SA_SMEM_FLOATS (2*128*TP + 128*SP)
#define SA_SMEM_BYTES  (SA_SMEM_FLOATS * 4)

__launch_bounds__(256)
__global__ void sa_attn_kernel(const float* __restrict__ qh,
                               const float* __restrict__ kh,
                               const float* __restrict__ vh,
                               const void*  __restrict__ mask,
                               float* __restrict__ out) {
    extern __shared__ float sm[];
    float* Qt = sm;
    float* Kt = sm + 128*TP;    // later reused for V
    float* Ss = sm + 2*128*TP;
    __shared__ float msk[128];

    const int bh = blockIdx.x;
    const int b = bh >> 1, h = bh & 1;
    const int tid = threadIdx.x;
    const size_t rowbase = (size_t)b * 128 * 256 + h * 128;

    for (int e = tid; e < 128*128; e += 256) {
        int r = e >> 7, c = e & 127;
        Qt[c*TP + r] = qh[rowbase + (size_t)r*256 + c];
        Kt[c*TP + r] = kh[rowbase + (size_t)r*256 + c];
    }
    if (tid < 128) msk[tid] = is_masked(mask, b*128 + tid) ? 1.f : 0.f;
    __syncthreads();

    const int tx = tid & 15, ty = tid >> 4;
    float acc[8][8];
#pragma unroll
    for (int i = 0; i < 8; i++)
#pragma unroll
        for (int j = 0; j < 8; j++) acc[i][j] = 0.f;

    // S = Q K^T
    for (int k = 0; k < 128; k++) {
        float a[8], bb[8];
        *(float4*)&a[0]  = *(const float4*)&Qt[k*TP + ty*8];
        *(float4*)&a[4]  = *(const float4*)&Qt[k*TP + ty*8 + 4];
        *(float4*)&bb[0] = *(const float4*)&Kt[k*TP + tx*8];
        *(float4*)&bb[4] = *(const float4*)&Kt[k*TP + tx*8 + 4];
#pragma unroll
        for (int i = 0; i < 8; i++)
#pragma unroll
            for (int j = 0; j < 8; j++)
                acc[i][j] = fmaf(a[i], bb[j], acc[i][j]);
    }
#pragma unroll
    for (int i = 0; i < 8; i++)
#pragma unroll
        for (int j = 0; j < 8; j++)
            Ss[(ty*8+i)*SP + tx*8 + j] = acc[i][j];
    __syncthreads();

    // softmax: warp per row
    {
        const int warp = tid >> 5, lane = tid & 31;
        for (int r = warp; r < 128; r += 8) {
            float v[4];
            float mx = -INFINITY;
#pragma unroll
            for (int u = 0; u < 4; u++) {
                int c = u*32 + lane;
                float s = Ss[r*SP + c];
                s = (msk[c] != 0.f) ? -1e10f : s * INV_SCALE;
                v[u] = s;
                mx = fmaxf(mx, s);
            }
#pragma unroll
            for (int o = 16; o; o >>= 1) mx = fmaxf(mx, __shfl_xor_sync(0xffffffffu, mx, o));
            float sum = 0.f;
#pragma unroll
            for (int u = 0; u < 4; u++) { v[u] = expf(v[u] - mx); sum += v[u]; }
#pragma unroll
            for (int o = 16; o; o >>= 1) sum += __shfl_xor_sync(0xffffffffu, sum, o);
            float inv = 1.f / sum;
#pragma unroll
            for (int u = 0; u < 4; u++) Ss[r*SP + u*32 + lane] = v[u] * inv;
        }
    }
    __syncthreads();

    // V into Kt region (natural layout)
    for (int e = tid; e < 128*128; e += 256) {
        int r = e >> 7, c = e & 127;
        Kt[r*TP + c] = vh[rowbase + (size_t)r*256 + c];
    }
    __syncthreads();

#pragma unroll
    for (int i = 0; i < 8; i++)
#pragma unroll
        for (int j = 0; j < 8; j++) acc[i][j] = 0.f;

    // O = P V
    for (int n = 0; n < 128; n++) {
        float a[8], bb[8];
#pragma unroll
        for (int i = 0; i < 8; i++) a[i] = Ss[(ty*8+i)*SP + n];
        *(float4*)&bb[0] = *(const float4*)&Kt[n*TP + tx*8];
        *(float4*)&bb[4] = *(const float4*)&Kt[n*TP + tx*8 + 4];
#pragma unroll
        for (int i = 0; i < 8; i++)
#pragma unroll
            for (int j = 0; j < 8; j++)
                acc[i][j] = fmaf(a[i], bb[j], acc[i][j]);
    }
#pragma unroll
    for (int i = 0; i < 8; i++)
#pragma unroll
        for (int j = 0; j < 8; j++)
            out[rowbase + (size_t)(ty*8+i)*256 + tx*8 + j] = acc[i][j];
}

// ---------------------------------------------------------------------------
// SA epilogue: x = tmp + fcb + kv_residual, LayerNorm(256). One warp per row.
// ---------------------------------------------------------------------------
__launch_bounds__(256)
__global__ void sa_ln_kernel(const float* __restrict__ tmp,
                             const float* __restrict__ fcb,
                             const float* __restrict__ seq,
                             const float* __restrict__ seq_t,
                             const float* __restrict__ lng,
                             const float* __restrict__ lnb,
                             float* __restrict__ outb) {
    const int warp = threadIdx.x >> 5, lane = threadIdx.x & 31;
    const size_t row = (size_t)blockIdx.x * 8 + warp;
    float v[8];
#pragma unroll
    for (int u = 0; u < 8; u++) {
        int c = u*32 + lane;
        float res = (c < 128) ? seq[row*128 + c] : seq_t[row*128 + (c-128)];
        v[u] = tmp[row*256 + c] + fcb[c] + res;
    }
    float s = 0.f;
#pragma unroll
    for (int u = 0; u < 8; u++) s += v[u];
#pragma unroll
    for (int o = 16; o; o >>= 1) s += __shfl_xor_sync(0xffffffffu, s, o);
    float m = s * (1.f/256.f);
    float q = 0.f;
#pragma unroll
    for (int u = 0; u < 8; u++) { float d = v[u] - m; q += d*d; }
#pragma unroll
    for (int o = 16; o; o >>= 1) q += __shfl_xor_sync(0xffffffffu, q, o);
    float inv = rsqrtf(q * (1.f/256.f) + LN_EPS);
#pragma unroll
    for (int u = 0; u < 8; u++) {
        int c = u*32 + lane;
        outb[row*256 + c] = (v[u] - m) * inv * lng[c] + lnb[c];
    }
}

// ---------------------------------------------------------------------------
// Cross-attention: one CTA per batch b (Lq = 1). Writes attn to d_out directly.
// ---------------------------------------------------------------------------
__launch_bounds__(256)
__global__ void ca_attn_kernel(const float* __restrict__ cq,
                               const float* __restrict__ ckh,
                               const float* __restrict__ cvh,
                               const void*  __restrict__ mask,
                               float* __restrict__ cao,
                               float* __restrict__ attn_out) {
    __shared__ float qs[256];
    __shared__ float sc[256];
    __shared__ float mred[2], sred[2];
    __shared__ float msk[128];
    const int b = blockIdx.x, t = threadIdx.x;

    qs[t] = cq[(size_t)b*256 + t];
    if (t < 128) msk[t] = is_masked(mask, b*128 + t) ? 1.f : 0.f;
    __syncthreads();

    const int h = t >> 7, n = t & 127;
    {
        const float4* k4 = (const float4*)(ckh + ((size_t)(b*128 + n))*256 + h*128);
        const float4* q4 = (const float4*)&qs[h*128];
        float s = 0.f;
#pragma unroll 8
        for (int k = 0; k < 32; k++) {
            float4 kv = k4[k], qv = q4[k];
            s += qv.x*kv.x + qv.y*kv.y + qv.z*kv.z + qv.w*kv.w;
        }
        s = (msk[n] != 0.f) ? -1e10f : s * INV_SCALE;
        sc[t] = s;
    }
    __syncthreads();

    const int warp = t >> 5, lane = t & 31;
    if (warp < 2) {
        float v[4]; float mx = -INFINITY;
#pragma unroll
        for (int u = 0; u < 4; u++) { v[u] = sc[warp*128 + u*32 + lane]; mx = fmaxf(mx, v[u]); }
#pragma unroll
        for (int o = 16; o; o >>= 1) mx = fmaxf(mx, __shfl_xor_sync(0xffffffffu, mx, o));
        float sum = 0.f;
#pragma unroll
        for (int u = 0; u < 4; u++) sum += expf(v[u] - mx);
#pragma unroll
        for (int o = 16; o; o >>= 1) sum += __shfl_xor_sync(0xffffffffu, sum, o);
        if (lane == 0) { mred[warp] = mx; sred[warp] = sum; }
    }
    __syncthreads();

    float p = expf(sc[t] - mred[h]) / sred[h];
    sc[t] = p;
    attn_out[((size_t)(h*BATCH + b))*128 + n] = p;
    __syncthreads();

    float acc = 0.f;
    const int hh = t >> 7;
    for (int nn = 0; nn < 128; nn++)
        acc = fmaf(sc[hh*128 + nn], cvh[((size_t)(b*128 + nn))*256 + t], acc);
    cao[(size_t)b*256 + t] = acc;
}

// ---------------------------------------------------------------------------
// CA epilogue: fc + bias + q-residual + LayerNorm. One CTA per b.
// ---------------------------------------------------------------------------
__launch_bounds__(256)
__global__ void ca_fc_ln_kernel(const float* __restrict__ cao,
                                const float* __restrict__ fcw,
                                const float* __restrict__ fcb,
                                const float* __restrict__ src,
                                const float* __restrict__ src_t,
                                const float* __restrict__ lng,
                                const float* __restrict__ lnb,
                                float* __restrict__ caout) {
    __shared__ float x[256];
    __shared__ float rbuf[8];
    __shared__ float stat[2];
    const int b = blockIdx.x, t = threadIdx.x;
    x[t] = cao[(size_t)b*256 + t];
    __syncthreads();

    float res = (t < 128) ? src[(size_t)b*128 + t] : src_t[(size_t)b*128 + (t-128)];
    float acc = fcb[t] + res;
    for (int k = 0; k < 256; k++)
        acc = fmaf(x[k], fcw[(size_t)k*256 + t], acc);

    float s = acc;
#pragma unroll
    for (int o = 16; o; o >>= 1) s += __shfl_xor_sync(0xffffffffu, s, o);
    if ((t & 31) == 0) rbuf[t >> 5] = s;
    __syncthreads();
    if (t == 0) {
        float tot = 0.f;
        for (int i = 0; i < 8; i++) tot += rbuf[i];
        stat[0] = tot * (1.f/256.f);
    }
    __syncthreads();
    float m = stat[0];
    float d = acc - m;
    float q = d*d;
#pragma unroll
    for (int o = 16; o; o >>= 1) q += __shfl_xor_sync(0xffffffffu, q, o);
    __syncthreads();
    if ((t & 31) == 0) rbuf[t >> 5] = q;
    __syncthreads();
    if (t == 0) {
        float tot = 0.f;
        for (int i = 0; i < 8; i++) tot += rbuf[i];
        stat[1] = rsqrtf(tot * (1.f/256.f) + LN_EPS);
    }
    __syncthreads();
    caout[(size_t)b*256 + t] = d * stat[1] * lng[t] + lnb[t];
}

// ---------------------------------------------------------------------------
// Final MLP: concat(ca_out, src) @ w1 +b1 relu @ w2 +b2. One CTA per b.
// ---------------------------------------------------------------------------
__launch_bounds__(128)
__global__ void mg_kernel(const float* __restrict__ caout,
                          const float* __restrict__ src,
                          const float* __restrict__ w1, const float* __restrict__ b1,
                          const float* __restrict__ w2, const float* __restrict__ b2,
                          float* __restrict__ out) {
    __shared__ float x[384];
    __shared__ float h1[128];
    const int b = blockIdx.x, t = threadIdx.x;
    x[t]       = caout[(size_t)b*256 + t];
    x[128 + t] = caout[(size_t)b*256 + 128 + t];
    x[256 + t] = src[(size_t)b*128 + t];
    __syncthreads();
    float acc = b1[t];
    for (int k = 0; k < 384; k++)
        acc = fmaf(x[k], w1[(size_t)k*128 + t], acc);
    h1[t] = fmaxf(acc, 0.f);
    __syncthreads();
    float o = b2[t];
    for (int k = 0; k < 128; k++)
        o = fmaf(h1[k], w2[(size_t)k*128 + t], o);
    out[(size_t)b*128 + t] = o;
}

// ---------------------------------------------------------------------------
// Launch
// ---------------------------------------------------------------------------
extern "C" void kernel_launch(void* const* d_in, const int* in_sizes, int n_in,
                              void* d_out, int out_size) {
    const float *src, *src_t, *seq, *seq_t;
    const void  *mask;
    const float *sa_wq, *sa_wk, *sa_wv, *sa_fcw, *sa_fcb, *sa_lng, *sa_lnb;
    const float *ms_w1, *ms_b1, *ms_w2, *ms_b2;
    const float *ca_wq, *ca_wk, *ca_wv, *ca_fcw, *ca_fcb, *ca_lng, *ca_lnb;
    const float *mg_w1, *mg_b1, *mg_w2, *mg_b2;

#define F(i) ((const float*)d_in[(i)])
    src = F(0); src_t = F(1); seq = F(2); seq_t = F(3); mask = d_in[4];
    if (in_sizes[10] == 98304) {
        // setup_inputs() dict order: ln params at positions matching dict insertion
        sa_wq = F(5); sa_wk = F(6); sa_wv = F(7); sa_fcw = F(8); sa_fcb = F(9);
        ms_w1 = F(10); ms_b1 = F(11); ms_w2 = F(12); ms_b2 = F(13);
        ca_wq = F(14); ca_wk = F(15); ca_wv = F(16); ca_fcw = F(17); ca_fcb = F(18);
        mg_w1 = F(19); mg_b1 = F(20); mg_w2 = F(21); mg_b2 = F(22);
        sa_lng = F(23); sa_lnb = F(24); ca_lng = F(25); ca_lnb = F(26);
    } else {
        // reference() signature order
        sa_wq = F(5); sa_wk = F(6); sa_wv = F(7); sa_fcw = F(8); sa_fcb = F(9);
        sa_lng = F(10); sa_lnb = F(11);
        ms_w1 = F(12); ms_b1 = F(13); ms_w2 = F(14); ms_b2 = F(15);
        ca_wq = F(16); ca_wk = F(17); ca_wv = F(18); ca_fcw = F(19); ca_fcb = F(20);
        ca_lng = F(21); ca_lnb = F(22);
        mg_w1 = F(23); mg_b1 = F(24); mg_w2 = F(25); mg_b2 = F(26);
    }
#undef F

    float* out      = (float*)d_out;
    float* attn_out = out + BATCH*FEAT;   // tuple flatten: out first, then attn

    float *U1,*U2,*U3,*U4,*U5,*cq,*cao,*cln;
    cudaGetSymbolAddress((void**)&U1, g_U1);
    cudaGetSymbolAddress((void**)&U2, g_U2);
    cudaGetSymbolAddress((void**)&U3, g_U3);
    cudaGetSymbolAddress((void**)&U4, g_U4);
    cudaGetSymbolAddress((void**)&U5, g_U5);
    cudaGetSymbolAddress((void**)&cq,  g_cq);
    cudaGetSymbolAddress((void**)&cao, g_cao);
    cudaGetSymbolAddress((void**)&cln, g_cln);

    // alias map (producer kernel fully precedes consumer kernel)
    float* qh  = U1;  float* sa  = U1;
    float* kh  = U2;  float* h1  = U2;
    float* vh  = U3;  float* k2  = U3;
    float* ao  = U4;  float* ckh = U4;
    float* tmp = U5;  float* cvh = U5;

    cudaFuncSetAttribute(sa_attn_kernel,
                         cudaFuncAttributeMaxDynamicSharedMemorySize, SA_SMEM_BYTES);

    detect_mask_kernel<<<1, 256>>>(mask);

    const dim3 gBig(2, ROWS/128);

    // SA projections: kv = [seq | seq_t]
    gemm128_kernel<0><<<gBig, 256>>>(seq, 128, seq_t, 128, sa_wq, nullptr, qh, 256);
    gemm128_kernel<0><<<gBig, 256>>>(seq, 128, seq_t, 128, sa_wk, nullptr, kh, 256);
    gemm128_kernel<0><<<gBig, 256>>>(seq, 128, seq_t, 128, sa_wv, nullptr, vh, 256);

    // SA attention
    sa_attn_kernel<<<BATCH*NHEAD, 256, SA_SMEM_BYTES>>>(qh, kh, vh, mask, ao);

    // SA fc + (bias + residual + LN)
    gemm128_kernel<0><<<gBig, 256>>>(ao, 256, nullptr, 0, sa_fcw, nullptr, tmp, 256);
    sa_ln_kernel<<<ROWS/8, 256>>>(tmp, sa_fcb, seq, seq_t, sa_lng, sa_lnb, sa);

    // MLP (ms): concat(sa, seq) -> relu -> linear
    gemm128_kernel<2><<<gBig, 256>>>(sa, 256, seq, 128, ms_w1, ms_b1, h1, 256);
    gemm128_kernel<1><<<gBig, 256>>>(h1, 256, nullptr, 0, ms_w2, ms_b2, k2, 256);

    // CA projections
    gemm128_kernel<0><<<gBig, 256>>>(k2, 256, nullptr, 0, ca_wk, nullptr, ckh, 256);
    gemm128_kernel<0><<<gBig, 256>>>(k2, 256, nullptr, 0, ca_wv, nullptr, cvh, 256);
    gemm128_kernel<0><<<dim3(2, BATCH/128), 256>>>(src, 128, src_t, 128, ca_wq, nullptr, cq, 256);

    // CA attention (writes attn part of d_out)
    ca_attn_kernel<<<BATCH, 256>>>(cq, ckh, cvh, mask, cao, attn_out);

    // CA fc + residual + LN
    ca_fc_ln_kernel<<<BATCH, 256>>>(cao, ca_fcw, ca_fcb, src, src_t, ca_lng, ca_lnb, cln);

    // Final MLP -> out part of d_out
    mg_kernel<<<BATCH, 128>>>(cln, src, mg_w1, mg_b1, mg_w2, mg_b2, out);
}

// round 5
// speedup vs baseline: 1.2181x; 1.2181x over previous
#include <cuda_runtime.h>
#include <cuda_bf16.h>
#include <math.h>
#include <stdint.h>

// ---------------------------------------------------------------------------
// Problem constants
// ---------------------------------------------------------------------------
#define BATCH   1024
#define NSEQ    128
#define FEAT    128
#define TIME    128
#define DMODEL  256
#define NHEAD   2
#define DK      128
#define ROWS    (BATCH*NSEQ)  // 131072

static const float LN_EPS    = 1e-5f;
static const float INV_SCALE = 0.08838834764831845f; // 1/sqrt(128)

// ---------------------------------------------------------------------------
// Scratch (device globals; aliased across kernel boundaries only)
// ---------------------------------------------------------------------------
__device__ float g_U1[ROWS*DMODEL];
__device__ float g_U2[ROWS*DMODEL];
__device__ float g_U3[ROWS*DMODEL];
__device__ float g_U4[ROWS*DMODEL];
__device__ float g_U5[ROWS*DMODEL];
__device__ float g_cq [BATCH*DMODEL];
__device__ float g_cao[BATCH*DMODEL];
__device__ float g_cln[BATCH*DMODEL];

// converted weights: bf16 hi/lo, transposed to [N][K] (k-major)
#define WOFF_SAWQ   0
#define WOFF_SAWK   65536
#define WOFF_SAWV   131072
#define WOFF_SAFCW  196608
#define WOFF_MSW1   262144   // 256x384
#define WOFF_MSW2   360448
#define WOFF_CAWQ   425984
#define WOFF_CAWK   491520
#define WOFF_CAWV   557056
#define WCONV_TOTAL 622592
__device__ __nv_bfloat16 g_whi[WCONV_TOTAL];
__device__ __nv_bfloat16 g_wlo[WCONV_TOTAL];

__device__ int g_mask_mode;  // 0/1 = 32-bit words, 2 = bytes

// ---------------------------------------------------------------------------
// Mask dtype detection
// ---------------------------------------------------------------------------
__global__ void detect_mask_kernel(const void* m) {
    __shared__ int bad_int, bad_flt;
    if (threadIdx.x == 0) { bad_int = 0; bad_flt = 0; }
    __syncthreads();
    const unsigned int* w = (const unsigned int*)m;
    int li = 0, lf = 0;
    for (int i = threadIdx.x; i < 32768; i += blockDim.x) {
        unsigned int v = w[i];
        if (v != 0u && v != 1u)           li = 1;
        if (v != 0u && v != 0x3F800000u)  lf = 1;
    }
    if (li) atomicOr(&bad_int, 1);
    if (lf) atomicOr(&bad_flt, 1);
    __syncthreads();
    if (threadIdx.x == 0)
        g_mask_mode = (!bad_int) ? 0 : ((!bad_flt) ? 1 : 2);
}
__device__ __forceinline__ bool is_masked(const void* m, int i) {
    if (g_mask_mode == 2) return ((const unsigned char*)m)[i] != 0;
    return ((const unsigned int*)m)[i] != 0u;
}

// ---------------------------------------------------------------------------
// Weight prep: w[K][N] fp32 -> whi/wlo[N][K] bf16 (hi/lo split), tiled transpose
// grid (N/32, K/32), block (32, 8)
// ---------------------------------------------------------------------------
__global__ void wsplit_kernel(const float* __restrict__ w, int K, int N,
                              __nv_bfloat16* __restrict__ whi,
                              __nv_bfloat16* __restrict__ wlo) {
    __shared__ float t[32][33];
    const int nb = blockIdx.x * 32, kb = blockIdx.y * 32;
    const int tx = threadIdx.x, ty = threadIdx.y;
#pragma unroll
    for (int i = 0; i < 32; i += 8)
        t[ty + i][tx] = w[(size_t)(kb + ty + i) * N + nb + tx];
    __syncthreads();
#pragma unroll
    for (int i = 0; i < 32; i += 8) {
        int n = nb + ty + i, k = kb + tx;
        float v = t[tx][ty + i];
        __nv_bfloat16 h = __float2bfloat16(v);
        whi[(size_t)n * K + k] = h;
        wlo[(size_t)n * K + k] = __float2bfloat16(v - __bfloat162float(h));
    }
}

// ---------------------------------------------------------------------------
// HMMA bf16 GEMM via mma.sync (works on base sm_100 target).
//   C[M,256] = [A0|A1] @ W  (+bias)(+relu), W pre-split hi/lo [N][K] k-major.
//   3-product accumulate: Ahi*Whi + Ahi*Wlo + Alo*Whi (rel err ~1.5e-5).
//   Block 128x128, 8 warps (2m x 4n), warp tile 64x32 = 4x4 m16n8k16 atoms.
//   K staged in 64-col chunks, SMEM [128][72] bf16 padded (conflict-free frags).
// ---------------------------------------------------------------------------
#define PAD 72
#define TILE_B (128*PAD*2)          // 18432 bytes per tile
#define GSM_AH 0
#define GSM_AL (TILE_B)
#define GSM_BH (2*TILE_B)
#define GSM_BL (3*TILE_B)
#define GEMM_SMEM_BYTES (4*TILE_B)  // 73728

__device__ __forceinline__ void mma16816(float* c, const uint32_t* a, const uint32_t* b) {
    asm volatile(
        "mma.sync.aligned.m16n8k16.row.col.f32.bf16.bf16.f32 "
        "{%0,%1,%2,%3}, {%4,%5,%6,%7}, {%8,%9}, {%0,%1,%2,%3};"
        : "+f"(c[0]), "+f"(c[1]), "+f"(c[2]), "+f"(c[3])
        : "r"(a[0]), "r"(a[1]), "r"(a[2]), "r"(a[3]), "r"(b[0]), "r"(b[1]));
}

template<int EPI>   // 0 none, 1 +bias, 2 +bias+relu
__launch_bounds__(256)
__global__ void hmma_gemm_kernel(const float* __restrict__ A0, int W0,
                                 const float* __restrict__ A1, int W1,
                                 const __nv_bfloat16* __restrict__ Whi,
                                 const __nv_bfloat16* __restrict__ Wlo,
                                 const float* __restrict__ bias,
                                 float* __restrict__ C) {
    extern __shared__ char smem[];
    __nv_bfloat16* Ah = (__nv_bfloat16*)(smem + GSM_AH);
    __nv_bfloat16* Al = (__nv_bfloat16*)(smem + GSM_AL);
    __nv_bfloat16* Bh = (__nv_bfloat16*)(smem + GSM_BH);
    __nv_bfloat16* Bl = (__nv_bfloat16*)(smem + GSM_BL);

    const int K   = W0 + W1;
    const int tid = threadIdx.x;
    const int wid = tid >> 5, lane = tid & 31;
    const int m0  = blockIdx.y * 128;
    const int n0  = blockIdx.x * 128;
    const int wm  = (wid >> 2) * 64;      // warp m offset (0/64)
    const int wn  = (wid & 3) * 32;       // warp n offset (0/32/64/96)

    float acc[4][4][4];
#pragma unroll
    for (int i = 0; i < 4; i++)
#pragma unroll
        for (int j = 0; j < 4; j++)
#pragma unroll
            for (int q = 0; q < 4; q++) acc[i][j][q] = 0.f;

    const int NCH = K >> 6;
    for (int c = 0; c < NCH; c++) {
        const int k0 = c * 64;
        // ---- A chunk: 128x64 fp32 -> bf16 hi/lo into padded SMEM ----
        {
            const float* Ab; int Wa, kk;
            if (k0 < W0) { Ab = A0; Wa = W0; kk = k0; }
            else         { Ab = A1; Wa = W1; kk = k0 - W0; }
#pragma unroll
            for (int i = 0; i < 8; i++) {
                int idx = tid + i * 256;            // 2048 float4 groups
                int row = idx >> 4, c4 = idx & 15;  // col = c4*4
                float4 v = *(const float4*)&Ab[(size_t)(m0 + row) * Wa + kk + c4 * 4];
                __nv_bfloat16 h0 = __float2bfloat16(v.x);
                __nv_bfloat16 h1 = __float2bfloat16(v.y);
                __nv_bfloat16 h2 = __float2bfloat16(v.z);
                __nv_bfloat16 h3 = __float2bfloat16(v.w);
                __nv_bfloat16 l0 = __float2bfloat16(v.x - __bfloat162float(h0));
                __nv_bfloat16 l1 = __float2bfloat16(v.y - __bfloat162float(h1));
                __nv_bfloat16 l2 = __float2bfloat16(v.z - __bfloat162float(h2));
                __nv_bfloat16 l3 = __float2bfloat16(v.w - __bfloat162float(h3));
                uint2 hp, lp;
                hp.x = (uint32_t)__bfloat16_as_ushort(h0) | ((uint32_t)__bfloat16_as_ushort(h1) << 16);
                hp.y = (uint32_t)__bfloat16_as_ushort(h2) | ((uint32_t)__bfloat16_as_ushort(h3) << 16);
                lp.x = (uint32_t)__bfloat16_as_ushort(l0) | ((uint32_t)__bfloat16_as_ushort(l1) << 16);
                lp.y = (uint32_t)__bfloat16_as_ushort(l2) | ((uint32_t)__bfloat16_as_ushort(l3) << 16);
                *(uint2*)&Ah[row * PAD + c4 * 4] = hp;
                *(uint2*)&Al[row * PAD + c4 * 4] = lp;
            }
        }
        // ---- B chunk: 128 n-rows x 64 k-cols bf16 hi/lo ----
#pragma unroll
        for (int i = 0; i < 8; i++) {
            int idx = tid + i * 256;
            int n = idx >> 4, c4 = idx & 15;
            uint2 vh = *(const uint2*)&Whi[(size_t)(n0 + n) * K + k0 + c4 * 4];
            uint2 vl = *(const uint2*)&Wlo[(size_t)(n0 + n) * K + k0 + c4 * 4];
            *(uint2*)&Bh[n * PAD + c4 * 4] = vh;
            *(uint2*)&Bl[n * PAD + c4 * 4] = vl;
        }
        __syncthreads();

        // ---- 4 k16-steps of HMMA ----
#pragma unroll
        for (int s = 0; s < 4; s++) {
            const int colb = s * 16 + (lane & 3) * 2;
            uint32_t bh[4][2], bl[4][2];
#pragma unroll
            for (int an = 0; an < 4; an++) {
                int nrow = wn + an * 8 + (lane >> 2);
                const uint32_t* ph = (const uint32_t*)&Bh[nrow * PAD + colb];
                const uint32_t* pl = (const uint32_t*)&Bl[nrow * PAD + colb];
                bh[an][0] = ph[0]; bh[an][1] = ph[4];   // k and k+8 (8 bf16 = 4 u32)
                bl[an][0] = pl[0]; bl[an][1] = pl[4];
            }
#pragma unroll
            for (int am = 0; am < 4; am++) {
                int arow = wm + am * 16 + (lane >> 2);
                const uint32_t* ph = (const uint32_t*)&Ah[arow * PAD + colb];
                const uint32_t* pl = (const uint32_t*)&Al[arow * PAD + colb];
                uint32_t ah[4], al[4];
                ah[0] = ph[0]; ah[1] = ph[8 * PAD / 2]; ah[2] = ph[4]; ah[3] = ph[8 * PAD / 2 + 4];
                al[0] = pl[0]; al[1] = pl[8 * PAD / 2]; al[2] = pl[4]; al[3] = pl[8 * PAD / 2 + 4];
#pragma unroll
                for (int an = 0; an < 4; an++) {
                    mma16816(acc[am][an], ah, bh[an]);
                    mma16816(acc[am][an], ah, bl[an]);
                    mma16816(acc[am][an], al, bh[an]);
                }
            }
        }
        __syncthreads();
    }

    // ---- epilogue ----
#pragma unroll
    for (int am = 0; am < 4; am++) {
#pragma unroll
        for (int an = 0; an < 4; an++) {
            int row = m0 + wm + am * 16 + (lane >> 2);
            int col = n0 + wn + an * 8 + (lane & 3) * 2;
            float b0 = 0.f, b1 = 0.f;
            if (EPI >= 1) { b0 = bias[col]; b1 = bias[col + 1]; }
            float v0 = acc[am][an][0] + b0, v1 = acc[am][an][1] + b1;
            float v2 = acc[am][an][2] + b0, v3 = acc[am][an][3] + b1;
            if (EPI == 2) {
                v0 = fmaxf(v0, 0.f); v1 = fmaxf(v1, 0.f);
                v2 = fmaxf(v2, 0.f); v3 = fmaxf(v3, 0.f);
            }
            *(float2*)&C[(size_t)row * 256 + col]       = make_float2(v0, v1);
            *(float2*)&C[(size_t)(row + 8) * 256 + col] = make_float2(v2, v3);
        }
    }
}

// ---------------------------------------------------------------------------
// Self-attention, one CTA per (b, h). All in SMEM (R2 version, passing).
// ---------------------------------------------------------------------------
#define TP 132
#define SP 129
#define SA_SMEM_BYTES ((2*128*TP + 128*SP) * 4)

__launch_bounds__(256)
__global__ void sa_attn_kernel(const float* __restrict__ qh,
                               const float* __restrict__ kh,
                               const float* __restrict__ vh,
                               const void*  __restrict__ mask,
                               float* __restrict__ out) {
    extern __shared__ float sm[];
    float* Qt = sm;
    float* Kt = sm + 128*TP;
    float* Ss = sm + 2*128*TP;
    __shared__ float msk[128];

    const int bh = blockIdx.x;
    const int b = bh >> 1, h = bh & 1;
    const int tid = threadIdx.x;
    const size_t rowbase = (size_t)b * 128 * 256 + h * 128;

    for (int e = tid; e < 128*128; e += 256) {
        int r = e >> 7, c = e & 127;
        Qt[c*TP + r] = qh[rowbase + (size_t)r*256 + c];
        Kt[c*TP + r] = kh[rowbase + (size_t)r*256 + c];
    }
    if (tid < 128) msk[tid] = is_masked(mask, b*128 + tid) ? 1.f : 0.f;
    __syncthreads();

    const int tx = tid & 15, ty = tid >> 4;
    float acc[8][8];
#pragma unroll
    for (int i = 0; i < 8; i++)
#pragma unroll
        for (int j = 0; j < 8; j++) acc[i][j] = 0.f;

    for (int k = 0; k < 128; k++) {
        float a[8], bb[8];
        *(float4*)&a[0]  = *(const float4*)&Qt[k*TP + ty*8];
        *(float4*)&a[4]  = *(const float4*)&Qt[k*TP + ty*8 + 4];
        *(float4*)&bb[0] = *(const float4*)&Kt[k*TP + tx*8];
        *(float4*)&bb[4] = *(const float4*)&Kt[k*TP + tx*8 + 4];
#pragma unroll
        for (int i = 0; i < 8; i++)
#pragma unroll
            for (int j = 0; j < 8; j++)
                acc[i][j] = fmaf(a[i], bb[j], acc[i][j]);
    }
#pragma unroll
    for (int i = 0; i < 8; i++)
#pragma unroll
        for (int j = 0; j < 8; j++)
            Ss[(ty*8+i)*SP + tx*8 + j] = acc[i][j];
    __syncthreads();

    {
        const int warp = tid >> 5, lane = tid & 31;
        for (int r = warp; r < 128; r += 8) {
            float v[4];
            float mx = -INFINITY;
#pragma unroll
            for (int u = 0; u < 4; u++) {
                int c = u*32 + lane;
                float s = Ss[r*SP + c];
                s = (msk[c] != 0.f) ? -1e10f : s * INV_SCALE;
                v[u] = s;
                mx = fmaxf(mx, s);
            }
#pragma unroll
            for (int o = 16; o; o >>= 1) mx = fmaxf(mx, __shfl_xor_sync(0xffffffffu, mx, o));
            float sum = 0.f;
#pragma unroll
            for (int u = 0; u < 4; u++) { v[u] = expf(v[u] - mx); sum += v[u]; }
#pragma unroll
            for (int o = 16; o; o >>= 1) sum += __shfl_xor_sync(0xffffffffu, sum, o);
            float inv = 1.f / sum;
#pragma unroll
            for (int u = 0; u < 4; u++) Ss[r*SP + u*32 + lane] = v[u] * inv;
        }
    }
    __syncthreads();

    for (int e = tid; e < 128*128; e += 256) {
        int r = e >> 7, c = e & 127;
        Kt[r*TP + c] = vh[rowbase + (size_t)r*256 + c];
    }
    __syncthreads();

#pragma unroll
    for (int i = 0; i < 8; i++)
#pragma unroll
        for (int j = 0; j < 8; j++) acc[i][j] = 0.f;

    for (int n = 0; n < 128; n++) {
        float a[8], bb[8];
#pragma unroll
        for (int i = 0; i < 8; i++) a[i] = Ss[(ty*8+i)*SP + n];
        *(float4*)&bb[0] = *(const float4*)&Kt[n*TP + tx*8];
        *(float4*)&bb[4] = *(const float4*)&Kt[n*TP + tx*8 + 4];
#pragma unroll
        for (int i = 0; i < 8; i++)
#pragma unroll
            for (int j = 0; j < 8; j++)
                acc[i][j] = fmaf(a[i], bb[j], acc[i][j]);
    }
#pragma unroll
    for (int i = 0; i < 8; i++)
#pragma unroll
        for (int j = 0; j < 8; j++)
            out[rowbase + (size_t)(ty*8+i)*256 + tx*8 + j] = acc[i][j];
}

// ---------------------------------------------------------------------------
// SA epilogue LN
// ---------------------------------------------------------------------------
__launch_bounds__(256)
__global__ void sa_ln_kernel(const float* __restrict__ tmp,
                             const float* __restrict__ fcb,
                             const float* __restrict__ seq,
                             const float* __restrict__ seq_t,
                             const float* __restrict__ lng,
                             const float* __restrict__ lnb,
                             float* __restrict__ outb) {
    const int warp = threadIdx.x >> 5, lane = threadIdx.x & 31;
    const size_t row = (size_t)blockIdx.x * 8 + warp;
    float v[8];
#pragma unroll
    for (int u = 0; u < 8; u++) {
        int c = u*32 + lane;
        float res = (c < 128) ? seq[row*128 + c] : seq_t[row*128 + (c-128)];
        v[u] = tmp[row*256 + c] + fcb[c] + res;
    }
    float s = 0.f;
#pragma unroll
    for (int u = 0; u < 8; u++) s += v[u];
#pragma unroll
    for (int o = 16; o; o >>= 1) s += __shfl_xor_sync(0xffffffffu, s, o);
    float m = s * (1.f/256.f);
    float q = 0.f;
#pragma unroll
    for (int u = 0; u < 8; u++) { float d = v[u] - m; q += d*d; }
#pragma unroll
    for (int o = 16; o; o >>= 1) q += __shfl_xor_sync(0xffffffffu, q, o);
    float inv = rsqrtf(q * (1.f/256.f) + LN_EPS);
#pragma unroll
    for (int u = 0; u < 8; u++) {
        int c = u*32 + lane;
        outb[row*256 + c] = (v[u] - m) * inv * lng[c] + lnb[c];
    }
}

// ---------------------------------------------------------------------------
// Cross-attention
// ---------------------------------------------------------------------------
__launch_bounds__(256)
__global__ void ca_attn_kernel(const float* __restrict__ cq,
                               const float* __restrict__ ckh,
                               const float* __restrict__ cvh,
                               const void*  __restrict__ mask,
                               float* __restrict__ cao,
                               float* __restrict__ attn_out) {
    __shared__ float qs[256];
    __shared__ float sc[256];
    __shared__ float mred[2], sred[2];
    __shared__ float msk[128];
    const int b = blockIdx.x, t = threadIdx.x;

    qs[t] = cq[(size_t)b*256 + t];
    if (t < 128) msk[t] = is_masked(mask, b*128 + t) ? 1.f : 0.f;
    __syncthreads();

    const int h = t >> 7, n = t & 127;
    {
        const float4* k4 = (const float4*)(ckh + ((size_t)(b*128 + n))*256 + h*128);
        const float4* q4 = (const float4*)&qs[h*128];
        float s = 0.f;
#pragma unroll 8
        for (int k = 0; k < 32; k++) {
            float4 kv = k4[k], qv = q4[k];
            s += qv.x*kv.x + qv.y*kv.y + qv.z*kv.z + qv.w*kv.w;
        }
        s = (msk[n] != 0.f) ? -1e10f : s * INV_SCALE;
        sc[t] = s;
    }
    __syncthreads();

    const int warp = t >> 5, lane = t & 31;
    if (warp < 2) {
        float v[4]; float mx = -INFINITY;
#pragma unroll
        for (int u = 0; u < 4; u++) { v[u] = sc[warp*128 + u*32 + lane]; mx = fmaxf(mx, v[u]); }
#pragma unroll
        for (int o = 16; o; o >>= 1) mx = fmaxf(mx, __shfl_xor_sync(0xffffffffu, mx, o));
        float sum = 0.f;
#pragma unroll
        for (int u = 0; u < 4; u++) sum += expf(v[u] - mx);
#pragma unroll
        for (int o = 16; o; o >>= 1) sum += __shfl_xor_sync(0xffffffffu, sum, o);
        if (lane == 0) { mred[warp] = mx; sred[warp] = sum; }
    }
    __syncthreads();

    float p = expf(sc[t] - mred[h]) / sred[h];
    sc[t] = p;
    attn_out[((size_t)(h*BATCH + b))*128 + n] = p;
    __syncthreads();

    float acc = 0.f;
    const int hh = t >> 7;
    for (int nn = 0; nn < 128; nn++)
        acc = fmaf(sc[hh*128 + nn], cvh[((size_t)(b*128 + nn))*256 + t], acc);
    cao[(size_t)b*256 + t] = acc;
}

// ---------------------------------------------------------------------------
// CA epilogue fc+LN
// ---------------------------------------------------------------------------
__launch_bounds__(256)
__global__ void ca_fc_ln_kernel(const float* __restrict__ cao,
                                const float* __restrict__ fcw,
                                const float* __restrict__ fcb,
                                const float* __restrict__ src,
                                const float* __restrict__ src_t,
                                const float* __restrict__ lng,
                                const float* __restrict__ lnb,
                                float* __restrict__ caout) {
    __shared__ float x[256];
    __shared__ float rbuf[8];
    __shared__ float stat[2];
    const int b = blockIdx.x, t = threadIdx.x;
    x[t] = cao[(size_t)b*256 + t];
    __syncthreads();

    float res = (t < 128) ? src[(size_t)b*128 + t] : src_t[(size_t)b*128 + (t-128)];
    float acc = fcb[t] + res;
    for (int k = 0; k < 256; k++)
        acc = fmaf(x[k], fcw[(size_t)k*256 + t], acc);

    float s = acc;
#pragma unroll
    for (int o = 16; o; o >>= 1) s += __shfl_xor_sync(0xffffffffu, s, o);
    if ((t & 31) == 0) rbuf[t >> 5] = s;
    __syncthreads();
    if (t == 0) {
        float tot = 0.f;
        for (int i = 0; i < 8; i++) tot += rbuf[i];
        stat[0] = tot * (1.f/256.f);
    }
    __syncthreads();
    float m = stat[0];
    float d = acc - m;
    float q = d*d;
#pragma unroll
    for (int o = 16; o; o >>= 1) q += __shfl_xor_sync(0xffffffffu, q, o);
    __syncthreads();
    if ((t & 31) == 0) rbuf[t >> 5] = q;
    __syncthreads();
    if (t == 0) {
        float tot = 0.f;
        for (int i = 0; i < 8; i++) tot += rbuf[i];
        stat[1] = rsqrtf(tot * (1.f/256.f) + LN_EPS);
    }
    __syncthreads();
    caout[(size_t)b*256 + t] = d * stat[1] * lng[t] + lnb[t];
}

// ---------------------------------------------------------------------------
// Final MLP
// ---------------------------------------------------------------------------
__launch_bounds__(128)
__global__ void mg_kernel(const float* __restrict__ caout,
                          const float* __restrict__ src,
                          const float* __restrict__ w1, const float* __restrict__ b1,
                          const float* __restrict__ w2, const float* __restrict__ b2,
                          float* __restrict__ out) {
    __shared__ float x[384];
    __shared__ float h1[128];
    const int b = blockIdx.x, t = threadIdx.x;
    x[t]       = caout[(size_t)b*256 + t];
    x[128 + t] = caout[(size_t)b*256 + 128 + t];
    x[256 + t] = src[(size_t)b*128 + t];
    __syncthreads();
    float acc = b1[t];
    for (int k = 0; k < 384; k++)
        acc = fmaf(x[k], w1[(size_t)k*128 + t], acc);
    h1[t] = fmaxf(acc, 0.f);
    __syncthreads();
    float o = b2[t];
    for (int k = 0; k < 128; k++)
        o = fmaf(h1[k], w2[(size_t)k*128 + t], o);
    out[(size_t)b*128 + t] = o;
}

// ---------------------------------------------------------------------------
// Launch
// ---------------------------------------------------------------------------
extern "C" void kernel_launch(void* const* d_in, const int* in_sizes, int n_in,
                              void* d_out, int out_size) {
    const float *src, *src_t, *seq, *seq_t;
    const void  *mask;
    const float *sa_wq, *sa_wk, *sa_wv, *sa_fcw, *sa_fcb, *sa_lng, *sa_lnb;
    const float *ms_w1, *ms_b1, *ms_w2, *ms_b2;
    const float *ca_wq, *ca_wk, *ca_wv, *ca_fcw, *ca_fcb, *ca_lng, *ca_lnb;
    const float *mg_w1, *mg_b1, *mg_w2, *mg_b2;

#define F(i) ((const float*)d_in[(i)])
    src = F(0); src_t = F(1); seq = F(2); seq_t = F(3); mask = d_in[4];
    if (in_sizes[10] == 98304) {
        sa_wq = F(5); sa_wk = F(6); sa_wv = F(7); sa_fcw = F(8); sa_fcb = F(9);
        ms_w1 = F(10); ms_b1 = F(11); ms_w2 = F(12); ms_b2 = F(13);
        ca_wq = F(14); ca_wk = F(15); ca_wv = F(16); ca_fcw = F(17); ca_fcb = F(18);
        mg_w1 = F(19); mg_b1 = F(20); mg_w2 = F(21); mg_b2 = F(22);
        sa_lng = F(23); sa_lnb = F(24); ca_lng = F(25); ca_lnb = F(26);
    } else {
        sa_wq = F(5); sa_wk = F(6); sa_wv = F(7); sa_fcw = F(8); sa_fcb = F(9);
        sa_lng = F(10); sa_lnb = F(11);
        ms_w1 = F(12); ms_b1 = F(13); ms_w2 = F(14); ms_b2 = F(15);
        ca_wq = F(16); ca_wk = F(17); ca_wv = F(18); ca_fcw = F(19); ca_fcb = F(20);
        ca_lng = F(21); ca_lnb = F(22);
        mg_w1 = F(23); mg_b1 = F(24); mg_w2 = F(25); mg_b2 = F(26);
    }
#undef F

    float* out      = (float*)d_out;
    float* attn_out = out + BATCH*FEAT;

    float *U1,*U2,*U3,*U4,*U5,*cq,*cao,*cln;
    __nv_bfloat16 *whi, *wlo;
    cudaGetSymbolAddress((void**)&U1, g_U1);
    cudaGetSymbolAddress((void**)&U2, g_U2);
    cudaGetSymbolAddress((void**)&U3, g_U3);
    cudaGetSymbolAddress((void**)&U4, g_U4);
    cudaGetSymbolAddress((void**)&U5, g_U5);
    cudaGetSymbolAddress((void**)&cq,  g_cq);
    cudaGetSymbolAddress((void**)&cao, g_cao);
    cudaGetSymbolAddress((void**)&cln, g_cln);
    cudaGetSymbolAddress((void**)&whi, g_whi);
    cudaGetSymbolAddress((void**)&wlo, g_wlo);

    float* qh  = U1;  float* sa  = U1;
    float* kh  = U2;  float* h1  = U2;
    float* vh  = U3;  float* k2  = U3;
    float* ao  = U4;  float* ckh = U4;
    float* tmp = U5;  float* cvh = U5;

    cudaFuncSetAttribute(sa_attn_kernel,
                         cudaFuncAttributeMaxDynamicSharedMemorySize, SA_SMEM_BYTES);
    cudaFuncSetAttribute(hmma_gemm_kernel<0>,
                         cudaFuncAttributeMaxDynamicSharedMemorySize, GEMM_SMEM_BYTES);
    cudaFuncSetAttribute(hmma_gemm_kernel<1>,
                         cudaFuncAttributeMaxDynamicSharedMemorySize, GEMM_SMEM_BYTES);
    cudaFuncSetAttribute(hmma_gemm_kernel<2>,
                         cudaFuncAttributeMaxDynamicSharedMemorySize, GEMM_SMEM_BYTES);

    detect_mask_kernel<<<1, 256>>>(mask);

    // ---- weight prep: fp32 [K][N] -> bf16 hi/lo [N][K] ----
    const dim3 wb(32, 8);
    wsplit_kernel<<<dim3(8,  8), wb>>>(sa_wq,  256, 256, whi+WOFF_SAWQ,  wlo+WOFF_SAWQ);
    wsplit_kernel<<<dim3(8,  8), wb>>>(sa_wk,  256, 256, whi+WOFF_SAWK,  wlo+WOFF_SAWK);
    wsplit_kernel<<<dim3(8,  8), wb>>>(sa_wv,  256, 256, whi+WOFF_SAWV,  wlo+WOFF_SAWV);
    wsplit_kernel<<<dim3(8,  8), wb>>>(sa_fcw, 256, 256, whi+WOFF_SAFCW, wlo+WOFF_SAFCW);
    wsplit_kernel<<<dim3(8, 12), wb>>>(ms_w1,  384, 256, whi+WOFF_MSW1,  wlo+WOFF_MSW1);
    wsplit_kernel<<<dim3(8,  8), wb>>>(ms_w2,  256, 256, whi+WOFF_MSW2,  wlo+WOFF_MSW2);
    wsplit_kernel<<<dim3(8,  8), wb>>>(ca_wq,  256, 256, whi+WOFF_CAWQ,  wlo+WOFF_CAWQ);
    wsplit_kernel<<<dim3(8,  8), wb>>>(ca_wk,  256, 256, whi+WOFF_CAWK,  wlo+WOFF_CAWK);
    wsplit_kernel<<<dim3(8,  8), wb>>>(ca_wv,  256, 256, whi+WOFF_CAWV,  wlo+WOFF_CAWV);

    const dim3 gBig(2, ROWS/128);   // N tiles x M tiles

    // SA projections: kv = [seq | seq_t]
    hmma_gemm_kernel<0><<<gBig, 256, GEMM_SMEM_BYTES>>>(seq, 128, seq_t, 128, whi+WOFF_SAWQ, wlo+WOFF_SAWQ, nullptr, qh);
    hmma_gemm_kernel<0><<<gBig, 256, GEMM_SMEM_BYTES>>>(seq, 128, seq_t, 128, whi+WOFF_SAWK, wlo+WOFF_SAWK, nullptr, kh);
    hmma_gemm_kernel<0><<<gBig, 256, GEMM_SMEM_BYTES>>>(seq, 128, seq_t, 128, whi+WOFF_SAWV, wlo+WOFF_SAWV, nullptr, vh);

    // SA attention
    sa_attn_kernel<<<BATCH*NHEAD, 256, SA_SMEM_BYTES>>>(qh, kh, vh, mask, ao);

    // SA fc, then bias+residual+LN
    hmma_gemm_kernel<0><<<gBig, 256, GEMM_SMEM_BYTES>>>(ao, 256, nullptr, 0, whi+WOFF_SAFCW, wlo+WOFF_SAFCW, nullptr, tmp);
    sa_ln_kernel<<<ROWS/8, 256>>>(tmp, sa_fcb, seq, seq_t, sa_lng, sa_lnb, sa);

    // MLP (ms): concat(sa, seq) -> relu -> linear
    hmma_gemm_kernel<2><<<gBig, 256, GEMM_SMEM_BYTES>>>(sa, 256, seq, 128, whi+WOFF_MSW1, wlo+WOFF_MSW1, ms_b1, h1);
    hmma_gemm_kernel<1><<<gBig, 256, GEMM_SMEM_BYTES>>>(h1, 256, nullptr, 0, whi+WOFF_MSW2, wlo+WOFF_MSW2, ms_b2, k2);

    // CA projections
    hmma_gemm_kernel<0><<<gBig, 256, GEMM_SMEM_BYTES>>>(k2, 256, nullptr, 0, whi+WOFF_CAWK, wlo+WOFF_CAWK, nullptr, ckh);
    hmma_gemm_kernel<0><<<gBig, 256, GEMM_SMEM_BYTES>>>(k2, 256, nullptr, 0, whi+WOFF_CAWV, wlo+WOFF_CAWV, nullptr, cvh);
    hmma_gemm_kernel<0><<<dim3(2, BATCH/128), 256, GEMM_SMEM_BYTES>>>(src, 128, src_t, 128, whi+WOFF_CAWQ, wlo+WOFF_CAWQ, nullptr, cq);

    // CA attention (writes attn part of d_out)
    ca_attn_kernel<<<BATCH, 256>>>(cq, ckh, cvh, mask, cao, attn_out);

    // CA fc + residual + LN
    ca_fc_ln_kernel<<<BATCH, 256>>>(cao, ca_fcw, ca_fcb, src, src_t, ca_lng, ca_lnb, cln);

    // Final MLP -> out part of d_out
    mg_kernel<<<BATCH, 128>>>(cln, src, mg_w1, mg_b1, mg_w2, mg_b2, out);
}

// round 7
// speedup vs baseline: 2.0991x; 1.7232x over previous
#include <cuda_runtime.h>
#include <cuda_bf16.h>
#include <math.h>
#include <stdint.h>

// ---------------------------------------------------------------------------
// Problem constants
// ---------------------------------------------------------------------------
#define BATCH   1024
#define NSEQ    128
#define FEAT    128
#define TIME    128
#define DMODEL  256
#define NHEAD   2
#define DK      128
#define ROWS    (BATCH*NSEQ)  // 131072

static const float LN_EPS    = 1e-5f;
static const float INV_SCALE = 0.08838834764831845f; // 1/sqrt(128)

__device__ __forceinline__ uint32_t pack_bf2(__nv_bfloat16 a, __nv_bfloat16 b) {
    return (uint32_t)__bfloat16_as_ushort(a) | ((uint32_t)__bfloat16_as_ushort(b) << 16);
}

// ---------------------------------------------------------------------------
// Scratch (device globals)
// ---------------------------------------------------------------------------
__device__ float g_qh [ROWS*DMODEL];
__device__ float g_kh [ROWS*DMODEL];
__device__ float g_vh [ROWS*DMODEL];
__device__ float g_tmp[ROWS*DMODEL];
__device__ float g_ckh[ROWS*DMODEL];
__device__ float g_cvh[ROWS*DMODEL];
__device__ float g_cq [BATCH*DMODEL];
__device__ float g_cao[BATCH*DMODEL];
__device__ float g_cln[BATCH*DMODEL];

// bf16 hi/lo split activations
__device__ __nv_bfloat16 g_seqh[ROWS*DMODEL], g_seql[ROWS*DMODEL];
__device__ __nv_bfloat16 g_aoh [ROWS*DMODEL], g_aol [ROWS*DMODEL];
__device__ __nv_bfloat16 g_sah [ROWS*DMODEL], g_sal [ROWS*DMODEL];
__device__ __nv_bfloat16 g_h1h [ROWS*DMODEL], g_h1l [ROWS*DMODEL];
__device__ __nv_bfloat16 g_k2h [ROWS*DMODEL], g_k2l [ROWS*DMODEL];
__device__ __nv_bfloat16 g_srch[BATCH*DMODEL], g_srcl[BATCH*DMODEL];

// converted weights: bf16 hi/lo, transposed to [N][K] (k-major)
#define WOFF_SAWQ   0        // [768][256] fused QKV block (wq,wk,wv contiguous)
#define WOFF_SAWK   65536
#define WOFF_SAWV   131072
#define WOFF_SAFCW  196608
#define WOFF_MSW1   262144   // [256][384]
#define WOFF_MSW2   360448
#define WOFF_CAWQ   425984
#define WOFF_CAWK   491520   // [512][256] fused CA K/V block
#define WOFF_CAWV   557056
#define WCONV_TOTAL 622592
__device__ __nv_bfloat16 g_whi[WCONV_TOTAL];
__device__ __nv_bfloat16 g_wlo[WCONV_TOTAL];

__device__ int g_mask_mode;  // 0/1 = 32-bit words, 2 = bytes

// ---------------------------------------------------------------------------
// Mask dtype detection
// ---------------------------------------------------------------------------
__global__ void detect_mask_kernel(const void* m) {
    __shared__ int bad_int, bad_flt;
    if (threadIdx.x == 0) { bad_int = 0; bad_flt = 0; }
    __syncthreads();
    const unsigned int* w = (const unsigned int*)m;
    int li = 0, lf = 0;
    for (int i = threadIdx.x; i < 32768; i += blockDim.x) {
        unsigned int v = w[i];
        if (v != 0u && v != 1u)           li = 1;
        if (v != 0u && v != 0x3F800000u)  lf = 1;
    }
    if (li) atomicOr(&bad_int, 1);
    if (lf) atomicOr(&bad_flt, 1);
    __syncthreads();
    if (threadIdx.x == 0)
        g_mask_mode = (!bad_int) ? 0 : ((!bad_flt) ? 1 : 2);
}
__device__ __forceinline__ bool is_masked(const void* m, int i) {
    if (g_mask_mode == 2) return ((const unsigned char*)m)[i] != 0;
    return ((const unsigned int*)m)[i] != 0u;
}

// ---------------------------------------------------------------------------
// Weight prep: w[K][N] fp32 -> whi/wlo[N][K] bf16 hi/lo, tiled transpose
// ---------------------------------------------------------------------------
__global__ void wsplit_kernel(const float* __restrict__ w, int K, int N,
                              __nv_bfloat16* __restrict__ whi,
                              __nv_bfloat16* __restrict__ wlo) {
    __shared__ float t[32][33];
    const int nb = blockIdx.x * 32, kb = blockIdx.y * 32;
    const int tx = threadIdx.x, ty = threadIdx.y;
#pragma unroll
    for (int i = 0; i < 32; i += 8)
        t[ty + i][tx] = w[(size_t)(kb + ty + i) * N + nb + tx];
    __syncthreads();
#pragma unroll
    for (int i = 0; i < 32; i += 8) {
        int n = nb + ty + i, k = kb + tx;
        float v = t[tx][ty + i];
        __nv_bfloat16 h = __float2bfloat16(v);
        whi[(size_t)n * K + k] = h;
        wlo[(size_t)n * K + k] = __float2bfloat16(v - __bfloat162float(h));
    }
}

// ---------------------------------------------------------------------------
// Activation split: concat(x0[M,128], x1[M,128]) -> hi/lo bf16 [M,256]
// ---------------------------------------------------------------------------
__global__ void split_concat_kernel(const float* __restrict__ x0,
                                    const float* __restrict__ x1,
                                    __nv_bfloat16* __restrict__ oh,
                                    __nv_bfloat16* __restrict__ ol) {
    int idx = blockIdx.x * 256 + threadIdx.x;      // M*64 total
    int row = idx >> 6, q = idx & 63;
    const float* src = (q < 32) ? &x0[(size_t)row * 128 + q * 4]
                                : &x1[(size_t)row * 128 + (q - 32) * 4];
    float4 v = *(const float4*)src;
    __nv_bfloat16 h0 = __float2bfloat16(v.x), h1 = __float2bfloat16(v.y);
    __nv_bfloat16 h2 = __float2bfloat16(v.z), h3 = __float2bfloat16(v.w);
    __nv_bfloat16 l0 = __float2bfloat16(v.x - __bfloat162float(h0));
    __nv_bfloat16 l1 = __float2bfloat16(v.y - __bfloat162float(h1));
    __nv_bfloat16 l2 = __float2bfloat16(v.z - __bfloat162float(h2));
    __nv_bfloat16 l3 = __float2bfloat16(v.w - __bfloat162float(h3));
    uint2 hp = make_uint2(pack_bf2(h0, h1), pack_bf2(h2, h3));
    uint2 lp = make_uint2(pack_bf2(l0, l1), pack_bf2(l2, l3));
    size_t off = (size_t)row * 256 + q * 4;
    *(uint2*)&oh[off] = hp;
    *(uint2*)&ol[off] = lp;
}

// ---------------------------------------------------------------------------
// HMMA GEMM, fully bf16 inputs, cp.async double-buffered, ldmatrix frags.
// ---------------------------------------------------------------------------
#define PAD   72
#define TB    (128*PAD*2)         // 18432 B per tile
#define STAGE (4*TB)              // 73728 B
#define GEMM_SMEM (2*STAGE)       // 147456 B

__device__ __forceinline__ void mma16816(float* c, const uint32_t* a, const uint32_t* b) {
    asm volatile(
        "mma.sync.aligned.m16n8k16.row.col.f32.bf16.bf16.f32 "
        "{%0,%1,%2,%3}, {%4,%5,%6,%7}, {%8,%9}, {%0,%1,%2,%3};"
        : "+f"(c[0]), "+f"(c[1]), "+f"(c[2]), "+f"(c[3])
        : "r"(a[0]), "r"(a[1]), "r"(a[2]), "r"(a[3]), "r"(b[0]), "r"(b[1]));
}
__device__ __forceinline__ void ldmx4(uint32_t* r, uint32_t a) {
    asm volatile("ldmatrix.sync.aligned.m8n8.x4.shared.b16 {%0,%1,%2,%3}, [%4];"
        : "=r"(r[0]), "=r"(r[1]), "=r"(r[2]), "=r"(r[3]) : "r"(a));
}
__device__ __forceinline__ void cp16(uint32_t dst, const void* src) {
    asm volatile("cp.async.cg.shared.global [%0], [%1], 16;" :: "r"(dst), "l"(src) : "memory");
}
#define CP_COMMIT() asm volatile("cp.async.commit_group;" ::: "memory")
#define CP_WAIT(n)  asm volatile("cp.async.wait_group %0;" :: "n"(n) : "memory")

__device__ __forceinline__ uint32_t smem_u32(const void* p) {
    uint32_t a;
    asm("{ .reg .u64 t; cvta.to.shared.u64 t, %1; cvt.u32.u64 %0, t; }" : "=r"(a) : "l"(p));
    return a;
}

// load one 128x64 bf16 tile pair (hi+lo) into smem (pitch PAD)
__device__ __forceinline__ void load_tile(uint32_t dh, uint32_t dl,
        const __nv_bfloat16* __restrict__ sh, const __nv_bfloat16* __restrict__ sl,
        int row0, int P, int ko, int tid) {
#pragma unroll
    for (int i = 0; i < 4; i++) {
        int idx = tid + i * 256;              // 0..1023
        int r = idx >> 3, seg = idx & 7;
        size_t g = (size_t)(row0 + r) * P + ko + seg * 8;
        uint32_t s = (uint32_t)(r * (PAD * 2) + seg * 16);
        cp16(dh + s, sh + g);
        cp16(dl + s, sl + g);
    }
}

template<int EPI, int OUT>   // EPI: 0 none,1 bias,2 bias+relu. OUT: 0 fp32, 1 bf16 split
__launch_bounds__(256, 1)
__global__ void hmma_gemm_kernel(
        const __nv_bfloat16* __restrict__ A0h, const __nv_bfloat16* __restrict__ A0l,
        int W0, int P0,
        const __nv_bfloat16* __restrict__ A1h, const __nv_bfloat16* __restrict__ A1l,
        int W1, int P1,
        const __nv_bfloat16* __restrict__ Bh_, const __nv_bfloat16* __restrict__ Bl_,
        const float* __restrict__ bias,
        float* __restrict__ C0, float* __restrict__ C1, float* __restrict__ C2,
        __nv_bfloat16* __restrict__ Ch, __nv_bfloat16* __restrict__ Cl) {
    extern __shared__ char smem[];
    const uint32_t sb = smem_u32(smem);
    const int K   = W0 + W1;
    const int tid = threadIdx.x;
    const int wid = tid >> 5, lane = tid & 31;
    const int m0  = blockIdx.y * 128;
    const int n0  = blockIdx.x * 128;
    const int wm  = (wid >> 2) * 64;
    const int wn  = (wid & 3) * 32;

    float acc[4][4][4];
#pragma unroll
    for (int i = 0; i < 4; i++)
#pragma unroll
        for (int j = 0; j < 4; j++)
#pragma unroll
            for (int q = 0; q < 4; q++) acc[i][j][q] = 0.f;

    const int NCH = K >> 6;

    auto issue_chunk = [&](int c, int st) {
        const int k0 = c * 64;
        uint32_t base = sb + st * STAGE;
        const __nv_bfloat16 *sh, *sl; int P, ko;
        if (k0 < W0) { sh = A0h; sl = A0l; P = P0; ko = k0; }
        else         { sh = A1h; sl = A1l; P = P1; ko = k0 - W0; }
        load_tile(base,          base + TB,     sh,  sl,  m0, P, ko, tid);
        load_tile(base + 2 * TB, base + 3 * TB, Bh_, Bl_, n0, K, k0, tid);
    };

    issue_chunk(0, 0);
    CP_COMMIT();

    const int aRow = lane & 15;
    const int aK   = (lane >> 4) * 8;
    const int bRow = (lane & 7) + ((lane >> 4) & 1) * 8;
    const int bK   = ((lane >> 3) & 1) * 8;

    for (int c = 0; c < NCH; c++) {
        if (c + 1 < NCH) { issue_chunk(c + 1, (c + 1) & 1); CP_COMMIT(); }
        if (c + 1 < NCH) { CP_WAIT(1); } else { CP_WAIT(0); }
        __syncthreads();

        const uint32_t st = sb + (c & 1) * STAGE;
        const uint32_t aA = st, lA = st + TB, aB = st + 2 * TB, lB = st + 3 * TB;
#pragma unroll
        for (int s = 0; s < 4; s++) {
            uint32_t bh[2][4], bl[2][4];
#pragma unroll
            for (int p = 0; p < 2; p++) {
                uint32_t off = (uint32_t)((wn + p * 16 + bRow) * PAD + s * 16 + bK) * 2;
                ldmx4(bh[p], aB + off);
                ldmx4(bl[p], lB + off);
            }
#pragma unroll
            for (int am = 0; am < 4; am++) {
                uint32_t off = (uint32_t)((wm + am * 16 + aRow) * PAD + s * 16 + aK) * 2;
                uint32_t ah[4], al[4];
                ldmx4(ah, aA + off);
                ldmx4(al, lA + off);
#pragma unroll
                for (int an = 0; an < 4; an++) {
                    const uint32_t* bhp = &bh[an >> 1][(an & 1) * 2];
                    const uint32_t* blp = &bl[an >> 1][(an & 1) * 2];
                    mma16816(acc[am][an], ah, bhp);
                    mma16816(acc[am][an], ah, blp);
                    mma16816(acc[am][an], al, bhp);
                }
            }
        }
        __syncthreads();
    }

    // ---- epilogue ----
    const int cidx = n0 >> 8;
    float* C = (cidx == 0) ? C0 : ((cidx == 1) ? C1 : C2);
    const int cb = n0 & 255;
#pragma unroll
    for (int am = 0; am < 4; am++) {
#pragma unroll
        for (int an = 0; an < 4; an++) {
            int row = m0 + wm + am * 16 + (lane >> 2);
            int col = cb + wn + an * 8 + (lane & 3) * 2;
            float b0 = 0.f, b1 = 0.f;
            if (EPI >= 1) { b0 = bias[col]; b1 = bias[col + 1]; }
            float v0 = acc[am][an][0] + b0, v1 = acc[am][an][1] + b1;
            float v2 = acc[am][an][2] + b0, v3 = acc[am][an][3] + b1;
            if (EPI == 2) {
                v0 = fmaxf(v0, 0.f); v1 = fmaxf(v1, 0.f);
                v2 = fmaxf(v2, 0.f); v3 = fmaxf(v3, 0.f);
            }
            if (OUT == 0) {
                *(float2*)&C[(size_t)row * 256 + col]       = make_float2(v0, v1);
                *(float2*)&C[(size_t)(row + 8) * 256 + col] = make_float2(v2, v3);
            } else {
                __nv_bfloat16 h0 = __float2bfloat16(v0), h1 = __float2bfloat16(v1);
                __nv_bfloat16 h2 = __float2bfloat16(v2), h3 = __float2bfloat16(v3);
                __nv_bfloat16 e0 = __float2bfloat16(v0 - __bfloat162float(h0));
                __nv_bfloat16 e1 = __float2bfloat16(v1 - __bfloat162float(h1));
                __nv_bfloat16 e2 = __float2bfloat16(v2 - __bfloat162float(h2));
                __nv_bfloat16 e3 = __float2bfloat16(v3 - __bfloat162float(h3));
                *(uint32_t*)&Ch[(size_t)row * 256 + col]       = pack_bf2(h0, h1);
                *(uint32_t*)&Cl[(size_t)row * 256 + col]       = pack_bf2(e0, e1);
                *(uint32_t*)&Ch[(size_t)(row + 8) * 256 + col] = pack_bf2(h2, h3);
                *(uint32_t*)&Cl[(size_t)(row + 8) * 256 + col] = pack_bf2(e2, e3);
            }
        }
    }
}

// ---------------------------------------------------------------------------
// Self-attention, one CTA per (b, h). Writes bf16 hi/lo output.
// ---------------------------------------------------------------------------
#define TP 132
#define SP 129
#define SA_SMEM_BYTES ((2*128*TP + 128*SP) * 4)

__launch_bounds__(256)
__global__ void sa_attn_kernel(const float* __restrict__ qh,
                               const float* __restrict__ kh,
                               const float* __restrict__ vh,
                               const void*  __restrict__ mask,
                               __nv_bfloat16* __restrict__ aoh,
                               __nv_bfloat16* __restrict__ aol) {
    extern __shared__ float sm[];
    float* Qt = sm;
    float* Kt = sm + 128*TP;
    float* Ss = sm + 2*128*TP;
    __shared__ float msk[128];

    const int bh = blockIdx.x;
    const int b = bh >> 1, h = bh & 1;
    const int tid = threadIdx.x;
    const size_t rowbase = (size_t)b * 128 * 256 + h * 128;

    for (int e = tid; e < 128*128; e += 256) {
        int r = e >> 7, c = e & 127;
        Qt[c*TP + r] = qh[rowbase + (size_t)r*256 + c];
        Kt[c*TP + r] = kh[rowbase + (size_t)r*256 + c];
    }
    if (tid < 128) msk[tid] = is_masked(mask, b*128 + tid) ? 1.f : 0.f;
    __syncthreads();

    const int tx = tid & 15, ty = tid >> 4;
    float acc[8][8];
#pragma unroll
    for (int i = 0; i < 8; i++)
#pragma unroll
        for (int j = 0; j < 8; j++) acc[i][j] = 0.f;

    for (int k = 0; k < 128; k++) {
        float a[8], bb[8];
        *(float4*)&a[0]  = *(const float4*)&Qt[k*TP + ty*8];
        *(float4*)&a[4]  = *(const float4*)&Qt[k*TP + ty*8 + 4];
        *(float4*)&bb[0] = *(const float4*)&Kt[k*TP + tx*8];
        *(float4*)&bb[4] = *(const float4*)&Kt[k*TP + tx*8 + 4];
#pragma unroll
        for (int i = 0; i < 8; i++)
#pragma unroll
            for (int j = 0; j < 8; j++)
                acc[i][j] = fmaf(a[i], bb[j], acc[i][j]);
    }
#pragma unroll
    for (int i = 0; i < 8; i++)
#pragma unroll
        for (int j = 0; j < 8; j++)
            Ss[(ty*8+i)*SP + tx*8 + j] = acc[i][j];
    __syncthreads();

    {
        const int warp = tid >> 5, lane = tid & 31;
        for (int r = warp; r < 128; r += 8) {
            float v[4];
            float mx = -INFINITY;
#pragma unroll
            for (int u = 0; u < 4; u++) {
                int c = u*32 + lane;
                float s = Ss[r*SP + c];
                s = (msk[c] != 0.f) ? -1e10f : s * INV_SCALE;
                v[u] = s;
                mx = fmaxf(mx, s);
            }
#pragma unroll
            for (int o = 16; o; o >>= 1) mx = fmaxf(mx, __shfl_xor_sync(0xffffffffu, mx, o));
            float sum = 0.f;
#pragma unroll
            for (int u = 0; u < 4; u++) { v[u] = expf(v[u] - mx); sum += v[u]; }
#pragma unroll
            for (int o = 16; o; o >>= 1) sum += __shfl_xor_sync(0xffffffffu, sum, o);
            float inv = 1.f / sum;
#pragma unroll
            for (int u = 0; u < 4; u++) Ss[r*SP + u*32 + lane] = v[u] * inv;
        }
    }
    __syncthreads();

    for (int e = tid; e < 128*128; e += 256) {
        int r = e >> 7, c = e & 127;
        Kt[r*TP + c] = vh[rowbase + (size_t)r*256 + c];
    }
    __syncthreads();

#pragma unroll
    for (int i = 0; i < 8; i++)
#pragma unroll
        for (int j = 0; j < 8; j++) acc[i][j] = 0.f;

    for (int n = 0; n < 128; n++) {
        float a[8], bb[8];
#pragma unroll
        for (int i = 0; i < 8; i++) a[i] = Ss[(ty*8+i)*SP + n];
        *(float4*)&bb[0] = *(const float4*)&Kt[n*TP + tx*8];
        *(float4*)&bb[4] = *(const float4*)&Kt[n*TP + tx*8 + 4];
#pragma unroll
        for (int i = 0; i < 8; i++)
#pragma unroll
            for (int j = 0; j < 8; j++)
                acc[i][j] = fmaf(a[i], bb[j], acc[i][j]);
    }
#pragma unroll
    for (int i = 0; i < 8; i++)
#pragma unroll
        for (int j = 0; j < 8; j += 2) {
            float v0 = acc[i][j], v1 = acc[i][j+1];
            __nv_bfloat16 h0 = __float2bfloat16(v0), h1 = __float2bfloat16(v1);
            __nv_bfloat16 l0 = __float2bfloat16(v0 - __bfloat162float(h0));
            __nv_bfloat16 l1 = __float2bfloat16(v1 - __bfloat162float(h1));
            size_t off = rowbase + (size_t)(ty*8+i)*256 + tx*8 + j;
            *(uint32_t*)&aoh[off] = pack_bf2(h0, h1);
            *(uint32_t*)&aol[off] = pack_bf2(l0, l1);
        }
}

// ---------------------------------------------------------------------------
// SA epilogue LN -> bf16 hi/lo output
// ---------------------------------------------------------------------------
__launch_bounds__(256)
__global__ void sa_ln_kernel(const float* __restrict__ tmp,
                             const float* __restrict__ fcb,
                             const float* __restrict__ seq,
                             const float* __restrict__ seq_t,
                             const float* __restrict__ lng,
                             const float* __restrict__ lnb,
                             __nv_bfloat16* __restrict__ sah,
                             __nv_bfloat16* __restrict__ sal) {
    const int warp = threadIdx.x >> 5, lane = threadIdx.x & 31;
    const size_t row = (size_t)blockIdx.x * 8 + warp;
    float v[8];
#pragma unroll
    for (int u = 0; u < 8; u++) {
        int c = u*32 + lane;
        float res = (c < 128) ? seq[row*128 + c] : seq_t[row*128 + (c-128)];
        v[u] = tmp[row*256 + c] + fcb[c] + res;
    }
    float s = 0.f;
#pragma unroll
    for (int u = 0; u < 8; u++) s += v[u];
#pragma unroll
    for (int o = 16; o; o >>= 1) s += __shfl_xor_sync(0xffffffffu, s, o);
    float m = s * (1.f/256.f);
    float q = 0.f;
#pragma unroll
    for (int u = 0; u < 8; u++) { float d = v[u] - m; q += d*d; }
#pragma unroll
    for (int o = 16; o; o >>= 1) q += __shfl_xor_sync(0xffffffffu, q, o);
    float inv = rsqrtf(q * (1.f/256.f) + LN_EPS);
#pragma unroll
    for (int u = 0; u < 8; u++) {
        int c = u*32 + lane;
        float y = (v[u] - m) * inv * lng[c] + lnb[c];
        __nv_bfloat16 h = __float2bfloat16(y);
        sah[row*256 + c] = h;
        sal[row*256 + c] = __float2bfloat16(y - __bfloat162float(h));
    }
}

// ---------------------------------------------------------------------------
// Cross-attention
// ---------------------------------------------------------------------------
__launch_bounds__(256)
__global__ void ca_attn_kernel(const float* __restrict__ cq,
                               const float* __restrict__ ckh,
                               const float* __restrict__ cvh,
                               const void*  __restrict__ mask,
                               float* __restrict__ cao,
                               float* __restrict__ attn_out) {
    __shared__ float qs[256];
    __shared__ float sc[256];
    __shared__ float mred[2], sred[2];
    __shared__ float msk[128];
    const int b = blockIdx.x, t = threadIdx.x;

    qs[t] = cq[(size_t)b*256 + t];
    if (t < 128) msk[t] = is_masked(mask, b*128 + t) ? 1.f : 0.f;
    __syncthreads();

    const int h = t >> 7, n = t & 127;
    {
        const float4* k4 = (const float4*)(ckh + ((size_t)(b*128 + n))*256 + h*128);
        const float4* q4 = (const float4*)&qs[h*128];
        float s = 0.f;
#pragma unroll 8
        for (int k = 0; k < 32; k++) {
            float4 kv = k4[k], qv = q4[k];
            s += qv.x*kv.x + qv.y*kv.y + qv.z*kv.z + qv.w*kv.w;
        }
        s = (msk[n] != 0.f) ? -1e10f : s * INV_SCALE;
        sc[t] = s;
    }
    __syncthreads();

    const int warp = t >> 5, lane = t & 31;
    if (warp < 2) {
        float v[4]; float mx = -INFINITY;
#pragma unroll
        for (int u = 0; u < 4; u++) { v[u] = sc[warp*128 + u*32 + lane]; mx = fmaxf(mx, v[u]); }
#pragma unroll
        for (int o = 16; o; o >>= 1) mx = fmaxf(mx, __shfl_xor_sync(0xffffffffu, mx, o));
        float sum = 0.f;
#pragma unroll
        for (int u = 0; u < 4; u++) sum += expf(v[u] - mx);
#pragma unroll
        for (int o = 16; o; o >>= 1) sum += __shfl_xor_sync(0xffffffffu, sum, o);
        if (lane == 0) { mred[warp] = mx; sred[warp] = sum; }
    }
    __syncthreads();

    float p = expf(sc[t] - mred[h]) / sred[h];
    sc[t] = p;
    attn_out[((size_t)(h*BATCH + b))*128 + n] = p;
    __syncthreads();

    float acc = 0.f;
    const int hh = t >> 7;
    for (int nn = 0; nn < 128; nn++)
        acc = fmaf(sc[hh*128 + nn], cvh[((size_t)(b*128 + nn))*256 + t], acc);
    cao[(size_t)b*256 + t] = acc;
}

// ---------------------------------------------------------------------------
// CA epilogue fc+LN
// ---------------------------------------------------------------------------
__launch_bounds__(256)
__global__ void ca_fc_ln_kernel(const float* __restrict__ cao,
                                const float* __restrict__ fcw,
                                const float* __restrict__ fcb,
                                const float* __restrict__ src,
                                const float* __restrict__ src_t,
                                const float* __restrict__ lng,
                                const float* __restrict__ lnb,
                                float* __restrict__ caout) {
    __shared__ float x[256];
    __shared__ float rbuf[8];
    __shared__ float stat[2];
    const int b = blockIdx.x, t = threadIdx.x;
    x[t] = cao[(size_t)b*256 + t];
    __syncthreads();

    float res = (t < 128) ? src[(size_t)b*128 + t] : src_t[(size_t)b*128 + (t-128)];
    float acc = fcb[t] + res;
    for (int k = 0; k < 256; k++)
        acc = fmaf(x[k], fcw[(size_t)k*256 + t], acc);

    float s = acc;
#pragma unroll
    for (int o = 16; o; o >>= 1) s += __shfl_xor_sync(0xffffffffu, s, o);
    if ((t & 31) == 0) rbuf[t >> 5] = s;
    __syncthreads();
    if (t == 0) {
        float tot = 0.f;
        for (int i = 0; i < 8; i++) tot += rbuf[i];
        stat[0] = tot * (1.f/256.f);
    }
    __syncthreads();
    float m = stat[0];
    float d = acc - m;
    float q = d*d;
#pragma unroll
    for (int o = 16; o; o >>= 1) q += __shfl_xor_sync(0xffffffffu, q, o);
    __syncthreads();
    if ((t & 31) == 0) rbuf[t >> 5] = q;
    __syncthreads();
    if (t == 0) {
        float tot = 0.f;
        for (int i = 0; i < 8; i++) tot += rbuf[i];
        stat[1] = rsqrtf(tot * (1.f/256.f) + LN_EPS);
    }
    __syncthreads();
    caout[(size_t)b*256 + t] = d * stat[1] * lng[t] + lnb[t];
}

// ---------------------------------------------------------------------------
// Final MLP
// ---------------------------------------------------------------------------
__launch_bounds__(128)
__global__ void mg_kernel(const float* __restrict__ caout,
                          const float* __restrict__ src,
                          const float* __restrict__ w1, const float* __restrict__ b1,
                          const float* __restrict__ w2, const float* __restrict__ b2,
                          float* __restrict__ out) {
    __shared__ float x[384];
    __shared__ float h1[128];
    const int b = blockIdx.x, t = threadIdx.x;
    x[t]       = caout[(size_t)b*256 + t];
    x[128 + t] = caout[(size_t)b*256 + 128 + t];
    x[256 + t] = src[(size_t)b*128 + t];
    __syncthreads();
    float acc = b1[t];
    for (int k = 0; k < 384; k++)
        acc = fmaf(x[k], w1[(size_t)k*128 + t], acc);
    h1[t] = fmaxf(acc, 0.f);
    __syncthreads();
    float o = b2[t];
    for (int k = 0; k < 128; k++)
        o = fmaf(h1[k], w2[(size_t)k*128 + t], o);
    out[(size_t)b*128 + t] = o;
}

// ---------------------------------------------------------------------------
// Launch
// ---------------------------------------------------------------------------
extern "C" void kernel_launch(void* const* d_in, const int* in_sizes, int n_in,
                              void* d_out, int out_size) {
    const float *src, *src_t, *seq, *seq_t;
    const void  *mask;
    const float *sa_wq, *sa_wk, *sa_wv, *sa_fcw, *sa_fcb, *sa_lng, *sa_lnb;
    const float *ms_w1, *ms_b1, *ms_w2, *ms_b2;
    const float *ca_wq, *ca_wk, *ca_wv, *ca_fcw, *ca_fcb, *ca_lng, *ca_lnb;
    const float *mg_w1, *mg_b1, *mg_w2, *mg_b2;

#define F(i) ((const float*)d_in[(i)])
    src = F(0); src_t = F(1); seq = F(2); seq_t = F(3); mask = d_in[4];
    if (in_sizes[10] == 98304) {
        sa_wq = F(5); sa_wk = F(6); sa_wv = F(7); sa_fcw = F(8); sa_fcb = F(9);
        ms_w1 = F(10); ms_b1 = F(11); ms_w2 = F(12); ms_b2 = F(13);
        ca_wq = F(14); ca_wk = F(15); ca_wv = F(16); ca_fcw = F(17); ca_fcb = F(18);
        mg_w1 = F(19); mg_b1 = F(20); mg_w2 = F(21); mg_b2 = F(22);
        sa_lng = F(23); sa_lnb = F(24); ca_lng = F(25); ca_lnb = F(26);
    } else {
        sa_wq = F(5); sa_wk = F(6); sa_wv = F(7); sa_fcw = F(8); sa_fcb = F(9);
        sa_lng = F(10); sa_lnb = F(11);
        ms_w1 = F(12); ms_b1 = F(13); ms_w2 = F(14); ms_b2 = F(15);
        ca_wq = F(16); ca_wk = F(17); ca_wv = F(18); ca_fcw = F(19); ca_fcb = F(20);
        ca_lng = F(21); ca_lnb = F(22);
        mg_w1 = F(23); mg_b1 = F(24); mg_w2 = F(25); mg_b2 = F(26);
    }
#undef F

    float* out      = (float*)d_out;
    float* attn_out = out + BATCH*FEAT;

    float *qh,*kh,*vh,*tmp,*ckh,*cvh,*cq,*cao,*cln;
    __nv_bfloat16 *whi,*wlo,*seqh,*seql,*aoh,*aol,*sah,*sal,*h1h,*h1l,*k2h,*k2l,*srch,*srcl;
    cudaGetSymbolAddress((void**)&qh,  g_qh);
    cudaGetSymbolAddress((void**)&kh,  g_kh);
    cudaGetSymbolAddress((void**)&vh,  g_vh);
    cudaGetSymbolAddress((void**)&tmp, g_tmp);
    cudaGetSymbolAddress((void**)&ckh, g_ckh);
    cudaGetSymbolAddress((void**)&cvh, g_cvh);
    cudaGetSymbolAddress((void**)&cq,  g_cq);
    cudaGetSymbolAddress((void**)&cao, g_cao);
    cudaGetSymbolAddress((void**)&cln, g_cln);
    cudaGetSymbolAddress((void**)&whi, g_whi);
    cudaGetSymbolAddress((void**)&wlo, g_wlo);
    cudaGetSymbolAddress((void**)&seqh, g_seqh);
    cudaGetSymbolAddress((void**)&seql, g_seql);
    cudaGetSymbolAddress((void**)&aoh, g_aoh);
    cudaGetSymbolAddress((void**)&aol, g_aol);
    cudaGetSymbolAddress((void**)&sah, g_sah);
    cudaGetSymbolAddress((void**)&sal, g_sal);
    cudaGetSymbolAddress((void**)&h1h, g_h1h);
    cudaGetSymbolAddress((void**)&h1l, g_h1l);
    cudaGetSymbolAddress((void**)&k2h, g_k2h);
    cudaGetSymbolAddress((void**)&k2l, g_k2l);
    cudaGetSymbolAddress((void**)&srch, g_srch);
    cudaGetSymbolAddress((void**)&srcl, g_srcl);

    cudaFuncSetAttribute(sa_attn_kernel,
                         cudaFuncAttributeMaxDynamicSharedMemorySize, SA_SMEM_BYTES);
    cudaFuncSetAttribute(hmma_gemm_kernel<0,0>,
                         cudaFuncAttributeMaxDynamicSharedMemorySize, GEMM_SMEM);
    cudaFuncSetAttribute(hmma_gemm_kernel<2,1>,
                         cudaFuncAttributeMaxDynamicSharedMemorySize, GEMM_SMEM);
    cudaFuncSetAttribute(hmma_gemm_kernel<1,1>,
                         cudaFuncAttributeMaxDynamicSharedMemorySize, GEMM_SMEM);

    detect_mask_kernel<<<1, 256>>>(mask);

    // activation splits for GEMM inputs
    split_concat_kernel<<<ROWS/4, 256>>>(seq, seq_t, seqh, seql);
    split_concat_kernel<<<BATCH/4, 256>>>(src, src_t, srch, srcl);

    // weight prep
    const dim3 wb(32, 8);
    wsplit_kernel<<<dim3(8,  8), wb>>>(sa_wq,  256, 256, whi+WOFF_SAWQ,  wlo+WOFF_SAWQ);
    wsplit_kernel<<<dim3(8,  8), wb>>>(sa_wk,  256, 256, whi+WOFF_SAWK,  wlo+WOFF_SAWK);
    wsplit_kernel<<<dim3(8,  8), wb>>>(sa_wv,  256, 256, whi+WOFF_SAWV,  wlo+WOFF_SAWV);
    wsplit_kernel<<<dim3(8,  8), wb>>>(sa_fcw, 256, 256, whi+WOFF_SAFCW, wlo+WOFF_SAFCW);
    wsplit_kernel<<<dim3(8, 12), wb>>>(ms_w1,  384, 256, whi+WOFF_MSW1,  wlo+WOFF_MSW1);
    wsplit_kernel<<<dim3(8,  8), wb>>>(ms_w2,  256, 256, whi+WOFF_MSW2,  wlo+WOFF_MSW2);
    wsplit_kernel<<<dim3(8,  8), wb>>>(ca_wq,  256, 256, whi+WOFF_CAWQ,  wlo+WOFF_CAWQ);
    wsplit_kernel<<<dim3(8,  8), wb>>>(ca_wk,  256, 256, whi+WOFF_CAWK,  wlo+WOFF_CAWK);
    wsplit_kernel<<<dim3(8,  8), wb>>>(ca_wv,  256, 256, whi+WOFF_CAWV,  wlo+WOFF_CAWV);

    // 1. fused QKV: [seq|seq_t] @ [wq;wk;wv]  (N=768)
    hmma_gemm_kernel<0,0><<<dim3(6, ROWS/128), 256, GEMM_SMEM>>>(
        seqh, seql, 256, 256, nullptr, nullptr, 0, 0,
        whi+WOFF_SAWQ, wlo+WOFF_SAWQ, nullptr, qh, kh, vh, nullptr, nullptr);

    // 2. SA attention -> ao split
    sa_attn_kernel<<<BATCH*NHEAD, 256, SA_SMEM_BYTES>>>(qh, kh, vh, mask, aoh, aol);

    // 3. SA fc
    hmma_gemm_kernel<0,0><<<dim3(2, ROWS/128), 256, GEMM_SMEM>>>(
        aoh, aol, 256, 256, nullptr, nullptr, 0, 0,
        whi+WOFF_SAFCW, wlo+WOFF_SAFCW, nullptr, tmp, nullptr, nullptr, nullptr, nullptr);

    // 4. bias+residual+LN -> sa split
    sa_ln_kernel<<<ROWS/8, 256>>>(tmp, sa_fcb, seq, seq_t, sa_lng, sa_lnb, sah, sal);

    // 5. MLP1: [sa | seq] @ ms_w1 +b1 relu -> h1 split  (K=384)
    hmma_gemm_kernel<2,1><<<dim3(2, ROWS/128), 256, GEMM_SMEM>>>(
        sah, sal, 256, 256, seqh, seql, 128, 256,
        whi+WOFF_MSW1, wlo+WOFF_MSW1, ms_b1, nullptr, nullptr, nullptr, h1h, h1l);

    // 6. MLP2 -> k2 split
    hmma_gemm_kernel<1,1><<<dim3(2, ROWS/128), 256, GEMM_SMEM>>>(
        h1h, h1l, 256, 256, nullptr, nullptr, 0, 0,
        whi+WOFF_MSW2, wlo+WOFF_MSW2, ms_b2, nullptr, nullptr, nullptr, k2h, k2l);

    // 7. fused CA K/V: k2 @ [cawk; cawv]  (N=512)
    hmma_gemm_kernel<0,0><<<dim3(4, ROWS/128), 256, GEMM_SMEM>>>(
        k2h, k2l, 256, 256, nullptr, nullptr, 0, 0,
        whi+WOFF_CAWK, wlo+WOFF_CAWK, nullptr, ckh, cvh, nullptr, nullptr, nullptr);

    // 8. CA Q: [src|src_t] @ ca_wq
    hmma_gemm_kernel<0,0><<<dim3(2, BATCH/128), 256, GEMM_SMEM>>>(
        srch, srcl, 256, 256, nullptr, nullptr, 0, 0,
        whi+WOFF_CAWQ, wlo+WOFF_CAWQ, nullptr, cq, nullptr, nullptr, nullptr, nullptr);

    // 9. CA attention (writes attn part of d_out)
    ca_attn_kernel<<<BATCH, 256>>>(cq, ckh, cvh, mask, cao, attn_out);

    // 10. CA fc + residual + LN
    ca_fc_ln_kernel<<<BATCH, 256>>>(cao, ca_fcw, ca_fcb, src, src_t, ca_lng, ca_lnb, cln);

    // 11. Final MLP -> out part of d_out
    mg_kernel<<<BATCH, 128>>>(cln, src, mg_w1, mg_b1, mg_w2, mg_b2, out);
}

// round 10
// speedup vs baseline: 2.4464x; 1.1654x over previous
#include <cuda_runtime.h>
#include <cuda_bf16.h>
#include <math.h>
#include <stdint.h>

// ---------------------------------------------------------------------------
// Problem constants
// ---------------------------------------------------------------------------
#define BATCH   1024
#define NSEQ    128
#define FEAT    128
#define TIME    128
#define DMODEL  256
#define NHEAD   2
#define DK      128
#define ROWS    (BATCH*NSEQ)  // 131072

static const float LN_EPS    = 1e-5f;
static const float INV_SCALE = 0.08838834764831845f; // 1/sqrt(128)

__device__ __forceinline__ uint32_t pack_bf2(__nv_bfloat16 a, __nv_bfloat16 b) {
    return (uint32_t)__bfloat16_as_ushort(a) | ((uint32_t)__bfloat16_as_ushort(b) << 16);
}

// ---------------------------------------------------------------------------
// Scratch (device globals)
// ---------------------------------------------------------------------------
__device__ float g_qh [ROWS*DMODEL];
__device__ float g_kh [ROWS*DMODEL];
__device__ float g_vh [ROWS*DMODEL];
__device__ float g_tmp[ROWS*DMODEL];
__device__ float g_ckh[ROWS*DMODEL];
__device__ float g_cvh[ROWS*DMODEL];
__device__ float g_cq [BATCH*DMODEL];
__device__ float g_cao[BATCH*DMODEL];
__device__ float g_cln[BATCH*DMODEL];

// bf16 hi/lo split activations
__device__ __nv_bfloat16 g_seqh[ROWS*DMODEL], g_seql[ROWS*DMODEL];
__device__ __nv_bfloat16 g_aoh [ROWS*DMODEL], g_aol [ROWS*DMODEL];
__device__ __nv_bfloat16 g_sah [ROWS*DMODEL], g_sal [ROWS*DMODEL];
__device__ __nv_bfloat16 g_h1h [ROWS*DMODEL], g_h1l [ROWS*DMODEL];
__device__ __nv_bfloat16 g_k2h [ROWS*DMODEL], g_k2l [ROWS*DMODEL];
__device__ __nv_bfloat16 g_srch[BATCH*DMODEL], g_srcl[BATCH*DMODEL];

// converted weights: bf16 hi/lo, transposed to [N][K] (k-major)
#define WOFF_SAWQ   0        // [768][256] fused QKV block
#define WOFF_SAWK   65536
#define WOFF_SAWV   131072
#define WOFF_SAFCW  196608
#define WOFF_MSW1   262144   // [256][384]
#define WOFF_MSW2   360448
#define WOFF_CAWQ   425984
#define WOFF_CAWK   491520   // [512][256] fused CA K/V block
#define WOFF_CAWV   557056
#define WCONV_TOTAL 622592
__device__ __nv_bfloat16 g_whi[WCONV_TOTAL];
__device__ __nv_bfloat16 g_wlo[WCONV_TOTAL];

__device__ int g_mask_mode;  // 0/1 = 32-bit words, 2 = bytes

// ---------------------------------------------------------------------------
// Mask dtype detection
// ---------------------------------------------------------------------------
__global__ void detect_mask_kernel(const void* m) {
    __shared__ int bad_int, bad_flt;
    if (threadIdx.x == 0) { bad_int = 0; bad_flt = 0; }
    __syncthreads();
    const unsigned int* w = (const unsigned int*)m;
    int li = 0, lf = 0;
    for (int i = threadIdx.x; i < 32768; i += blockDim.x) {
        unsigned int v = w[i];
        if (v != 0u && v != 1u)           li = 1;
        if (v != 0u && v != 0x3F800000u)  lf = 1;
    }
    if (li) atomicOr(&bad_int, 1);
    if (lf) atomicOr(&bad_flt, 1);
    __syncthreads();
    if (threadIdx.x == 0)
        g_mask_mode = (!bad_int) ? 0 : ((!bad_flt) ? 1 : 2);
}
__device__ __forceinline__ bool is_masked(const void* m, int i) {
    if (g_mask_mode == 2) return ((const unsigned char*)m)[i] != 0;
    return ((const unsigned int*)m)[i] != 0u;
}

// ---------------------------------------------------------------------------
// Weight prep
// ---------------------------------------------------------------------------
__global__ void wsplit_kernel(const float* __restrict__ w, int K, int N,
                              __nv_bfloat16* __restrict__ whi,
                              __nv_bfloat16* __restrict__ wlo) {
    __shared__ float t[32][33];
    const int nb = blockIdx.x * 32, kb = blockIdx.y * 32;
    const int tx = threadIdx.x, ty = threadIdx.y;
#pragma unroll
    for (int i = 0; i < 32; i += 8)
        t[ty + i][tx] = w[(size_t)(kb + ty + i) * N + nb + tx];
    __syncthreads();
#pragma unroll
    for (int i = 0; i < 32; i += 8) {
        int n = nb + ty + i, k = kb + tx;
        float v = t[tx][ty + i];
        __nv_bfloat16 h = __float2bfloat16(v);
        whi[(size_t)n * K + k] = h;
        wlo[(size_t)n * K + k] = __float2bfloat16(v - __bfloat162float(h));
    }
}

// ---------------------------------------------------------------------------
// Activation split: concat(x0[M,128], x1[M,128]) -> hi/lo bf16 [M,256]
// ---------------------------------------------------------------------------
__global__ void split_concat_kernel(const float* __restrict__ x0,
                                    const float* __restrict__ x1,
                                    __nv_bfloat16* __restrict__ oh,
                                    __nv_bfloat16* __restrict__ ol) {
    int idx = blockIdx.x * 256 + threadIdx.x;
    int row = idx >> 6, q = idx & 63;
    const float* src = (q < 32) ? &x0[(size_t)row * 128 + q * 4]
                                : &x1[(size_t)row * 128 + (q - 32) * 4];
    float4 v = *(const float4*)src;
    __nv_bfloat16 h0 = __float2bfloat16(v.x), h1 = __float2bfloat16(v.y);
    __nv_bfloat16 h2 = __float2bfloat16(v.z), h3 = __float2bfloat16(v.w);
    __nv_bfloat16 l0 = __float2bfloat16(v.x - __bfloat162float(h0));
    __nv_bfloat16 l1 = __float2bfloat16(v.y - __bfloat162float(h1));
    __nv_bfloat16 l2 = __float2bfloat16(v.z - __bfloat162float(h2));
    __nv_bfloat16 l3 = __float2bfloat16(v.w - __bfloat162float(h3));
    uint2 hp = make_uint2(pack_bf2(h0, h1), pack_bf2(h2, h3));
    uint2 lp = make_uint2(pack_bf2(l0, l1), pack_bf2(l2, l3));
    size_t off = (size_t)row * 256 + q * 4;
    *(uint2*)&oh[off] = hp;
    *(uint2*)&ol[off] = lp;
}

// ---------------------------------------------------------------------------
// Shared HMMA primitives
// ---------------------------------------------------------------------------
#define PAD   72
#define TB    (128*PAD*2)
#define STAGE (4*TB)
#define GEMM_SMEM (2*STAGE)       // 147456 B

__device__ __forceinline__ void mma16816(float* c, const uint32_t* a, const uint32_t* b) {
    asm volatile(
        "mma.sync.aligned.m16n8k16.row.col.f32.bf16.bf16.f32 "
        "{%0,%1,%2,%3}, {%4,%5,%6,%7}, {%8,%9}, {%0,%1,%2,%3};"
        : "+f"(c[0]), "+f"(c[1]), "+f"(c[2]), "+f"(c[3])
        : "r"(a[0]), "r"(a[1]), "r"(a[2]), "r"(a[3]), "r"(b[0]), "r"(b[1]));
}
__device__ __forceinline__ void ldmx4(uint32_t* r, uint32_t a) {
    asm volatile("ldmatrix.sync.aligned.m8n8.x4.shared.b16 {%0,%1,%2,%3}, [%4];"
        : "=r"(r[0]), "=r"(r[1]), "=r"(r[2]), "=r"(r[3]) : "r"(a));
}
__device__ __forceinline__ void cp16(uint32_t dst, const void* src) {
    asm volatile("cp.async.cg.shared.global [%0], [%1], 16;" :: "r"(dst), "l"(src) : "memory");
}
#define CP_COMMIT() asm volatile("cp.async.commit_group;" ::: "memory")
#define CP_WAIT(n)  asm volatile("cp.async.wait_group %0;" :: "n"(n) : "memory")

__device__ __forceinline__ uint32_t smem_u32(const void* p) {
    uint32_t a;
    asm("{ .reg .u64 t; cvta.to.shared.u64 t, %1; cvt.u32.u64 %0, t; }" : "=r"(a) : "l"(p));
    return a;
}

__device__ __forceinline__ void load_tile(uint32_t dh, uint32_t dl,
        const __nv_bfloat16* __restrict__ sh, const __nv_bfloat16* __restrict__ sl,
        int row0, int P, int ko, int tid) {
#pragma unroll
    for (int i = 0; i < 4; i++) {
        int idx = tid + i * 256;
        int r = idx >> 3, seg = idx & 7;
        size_t g = (size_t)(row0 + r) * P + ko + seg * 8;
        uint32_t s = (uint32_t)(r * (PAD * 2) + seg * 16);
        cp16(dh + s, sh + g);
        cp16(dl + s, sl + g);
    }
}

// ---------------------------------------------------------------------------
// HMMA GEMM (unchanged from the 2546us R7 PASS)
// ---------------------------------------------------------------------------
template<int EPI, int OUT>
__launch_bounds__(256, 1)
__global__ void hmma_gemm_kernel(
        const __nv_bfloat16* __restrict__ A0h, const __nv_bfloat16* __restrict__ A0l,
        int W0, int P0,
        const __nv_bfloat16* __restrict__ A1h, const __nv_bfloat16* __restrict__ A1l,
        int W1, int P1,
        const __nv_bfloat16* __restrict__ Bh_, const __nv_bfloat16* __restrict__ Bl_,
        const float* __restrict__ bias,
        float* __restrict__ C0, float* __restrict__ C1, float* __restrict__ C2,
        __nv_bfloat16* __restrict__ Ch, __nv_bfloat16* __restrict__ Cl) {
    extern __shared__ char smem[];
    const uint32_t sb = smem_u32(smem);
    const int K   = W0 + W1;
    const int tid = threadIdx.x;
    const int wid = tid >> 5, lane = tid & 31;
    const int m0  = blockIdx.y * 128;
    const int n0  = blockIdx.x * 128;
    const int wm  = (wid >> 2) * 64;
    const int wn  = (wid & 3) * 32;

    float acc[4][4][4];
#pragma unroll
    for (int i = 0; i < 4; i++)
#pragma unroll
        for (int j = 0; j < 4; j++)
#pragma unroll
            for (int q = 0; q < 4; q++) acc[i][j][q] = 0.f;

    const int NCH = K >> 6;

    auto issue_chunk = [&](int c, int st) {
        const int k0 = c * 64;
        uint32_t base = sb + st * STAGE;
        const __nv_bfloat16 *sh, *sl; int P, ko;
        if (k0 < W0) { sh = A0h; sl = A0l; P = P0; ko = k0; }
        else         { sh = A1h; sl = A1l; P = P1; ko = k0 - W0; }
        load_tile(base,          base + TB,     sh,  sl,  m0, P, ko, tid);
        load_tile(base + 2 * TB, base + 3 * TB, Bh_, Bl_, n0, K, k0, tid);
    };

    issue_chunk(0, 0);
    CP_COMMIT();

    const int aRow = lane & 15;
    const int aK   = (lane >> 4) * 8;
    const int bRow = (lane & 7) + ((lane >> 4) & 1) * 8;
    const int bK   = ((lane >> 3) & 1) * 8;

    for (int c = 0; c < NCH; c++) {
        if (c + 1 < NCH) { issue_chunk(c + 1, (c + 1) & 1); CP_COMMIT(); }
        if (c + 1 < NCH) { CP_WAIT(1); } else { CP_WAIT(0); }
        __syncthreads();

        const uint32_t st = sb + (c & 1) * STAGE;
        const uint32_t aA = st, lA = st + TB, aB = st + 2 * TB, lB = st + 3 * TB;
#pragma unroll
        for (int s = 0; s < 4; s++) {
            uint32_t bh[2][4], bl[2][4];
#pragma unroll
            for (int p = 0; p < 2; p++) {
                uint32_t off = (uint32_t)((wn + p * 16 + bRow) * PAD + s * 16 + bK) * 2;
                ldmx4(bh[p], aB + off);
                ldmx4(bl[p], lB + off);
            }
#pragma unroll
            for (int am = 0; am < 4; am++) {
                uint32_t off = (uint32_t)((wm + am * 16 + aRow) * PAD + s * 16 + aK) * 2;
                uint32_t ah[4], al[4];
                ldmx4(ah, aA + off);
                ldmx4(al, lA + off);
#pragma unroll
                for (int an = 0; an < 4; an++) {
                    const uint32_t* bhp = &bh[an >> 1][(an & 1) * 2];
                    const uint32_t* blp = &bl[an >> 1][(an & 1) * 2];
                    mma16816(acc[am][an], ah, bhp);
                    mma16816(acc[am][an], ah, blp);
                    mma16816(acc[am][an], al, bhp);
                }
            }
        }
        __syncthreads();
    }

    const int cidx = n0 >> 8;
    float* C = (cidx == 0) ? C0 : ((cidx == 1) ? C1 : C2);
    const int cb = n0 & 255;
#pragma unroll
    for (int am = 0; am < 4; am++) {
#pragma unroll
        for (int an = 0; an < 4; an++) {
            int row = m0 + wm + am * 16 + (lane >> 2);
            int col = cb + wn + an * 8 + (lane & 3) * 2;
            float b0 = 0.f, b1 = 0.f;
            if (EPI >= 1) { b0 = bias[col]; b1 = bias[col + 1]; }
            float v0 = acc[am][an][0] + b0, v1 = acc[am][an][1] + b1;
            float v2 = acc[am][an][2] + b0, v3 = acc[am][an][3] + b1;
            if (EPI == 2) {
                v0 = fmaxf(v0, 0.f); v1 = fmaxf(v1, 0.f);
                v2 = fmaxf(v2, 0.f); v3 = fmaxf(v3, 0.f);
            }
            if (OUT == 0) {
                *(float2*)&C[(size_t)row * 256 + col]       = make_float2(v0, v1);
                *(float2*)&C[(size_t)(row + 8) * 256 + col] = make_float2(v2, v3);
            } else {
                __nv_bfloat16 h0 = __float2bfloat16(v0), h1 = __float2bfloat16(v1);
                __nv_bfloat16 h2 = __float2bfloat16(v2), h3 = __float2bfloat16(v3);
                __nv_bfloat16 e0 = __float2bfloat16(v0 - __bfloat162float(h0));
                __nv_bfloat16 e1 = __float2bfloat16(v1 - __bfloat162float(h1));
                __nv_bfloat16 e2 = __float2bfloat16(v2 - __bfloat162float(h2));
                __nv_bfloat16 e3 = __float2bfloat16(v3 - __bfloat162float(h3));
                *(uint32_t*)&Ch[(size_t)row * 256 + col]       = pack_bf2(h0, h1);
                *(uint32_t*)&Cl[(size_t)row * 256 + col]       = pack_bf2(e0, e1);
                *(uint32_t*)&Ch[(size_t)(row + 8) * 256 + col] = pack_bf2(h2, h3);
                *(uint32_t*)&Cl[(size_t)(row + 8) * 256 + col] = pack_bf2(e2, e3);
            }
        }
    }
}

// ---------------------------------------------------------------------------
// Self-attention via HMMA, one CTA per (b, h).
// FIXED: attention tiles hold 128 k-entries per row -> own pitch APAD=136
// (272 B row stride = 16 mod 128 -> same conflict-free ldmatrix property).
// SMEM: Qh|Ql|Kh|Kl (128x136 bf16 each = 34816 B) + Ss (128x129 f32)
// Total 4*34816 + 66048 = 205312 B <= 227KB.
// ---------------------------------------------------------------------------
#define APAD 136
#define ATB  (128*APAD*2)     // 34816
#define SP2  129
#define ASM_QH 0
#define ASM_QL (ATB)
#define ASM_KH (2*ATB)
#define ASM_KL (3*ATB)
#define ASM_SS (4*ATB)
#define SA_SMEM_BYTES (4*ATB + 128*SP2*4)   // 205312

__launch_bounds__(256, 1)
__global__ void sa_attn_kernel(const float* __restrict__ qh,
                               const float* __restrict__ kh,
                               const float* __restrict__ vh,
                               const void*  __restrict__ mask,
                               __nv_bfloat16* __restrict__ aoh,
                               __nv_bfloat16* __restrict__ aol) {
    extern __shared__ char smem[];
    const uint32_t sb = smem_u32(smem);
    float* Ss = (float*)(smem + ASM_SS);
    __shared__ float msk[128];

    const int bh = blockIdx.x;
    const int b = bh >> 1, h = bh & 1;
    const int tid = threadIdx.x;
    const int wid = tid >> 5, lane = tid & 31;
    const size_t rowbase = (size_t)b * 128 * 256 + h * 128;
    const int wm = (wid >> 2) * 64;
    const int wn = (wid & 3) * 32;

    // ---- Phase A0: load Q, K -> bf16 hi/lo SMEM [row][k], pitch APAD ----
    {
        __nv_bfloat16* Qh = (__nv_bfloat16*)(smem + ASM_QH);
        __nv_bfloat16* Ql = (__nv_bfloat16*)(smem + ASM_QL);
        __nv_bfloat16* Kh = (__nv_bfloat16*)(smem + ASM_KH);
        __nv_bfloat16* Kl = (__nv_bfloat16*)(smem + ASM_KL);
#pragma unroll
        for (int i = 0; i < 16; i++) {
            int idx = tid + i * 256;          // 4096 float4 jobs
            int row = idx >> 5, c4 = idx & 31;
            size_t g = rowbase + (size_t)row * 256 + c4 * 4;
            float4 q = *(const float4*)&qh[g];
            float4 k = *(const float4*)&kh[g];
            int so = row * APAD + c4 * 4;     // c4*4 <= 124 < 136
            __nv_bfloat16 h0, h1, h2, h3;
            h0 = __float2bfloat16(q.x); h1 = __float2bfloat16(q.y);
            h2 = __float2bfloat16(q.z); h3 = __float2bfloat16(q.w);
            *(uint2*)&Qh[so] = make_uint2(pack_bf2(h0, h1), pack_bf2(h2, h3));
            *(uint2*)&Ql[so] = make_uint2(
                pack_bf2(__float2bfloat16(q.x - __bfloat162float(h0)),
                         __float2bfloat16(q.y - __bfloat162float(h1))),
                pack_bf2(__float2bfloat16(q.z - __bfloat162float(h2)),
                         __float2bfloat16(q.w - __bfloat162float(h3))));
            h0 = __float2bfloat16(k.x); h1 = __float2bfloat16(k.y);
            h2 = __float2bfloat16(k.z); h3 = __float2bfloat16(k.w);
            *(uint2*)&Kh[so] = make_uint2(pack_bf2(h0, h1), pack_bf2(h2, h3));
            *(uint2*)&Kl[so] = make_uint2(
                pack_bf2(__float2bfloat16(k.x - __bfloat162float(h0)),
                         __float2bfloat16(k.y - __bfloat162float(h1))),
                pack_bf2(__float2bfloat16(k.z - __bfloat162float(h2)),
                         __float2bfloat16(k.w - __bfloat162float(h3))));
        }
    }
    if (tid < 128) msk[tid] = is_masked(mask, b * 128 + tid) ? 1.f : 0.f;
    __syncthreads();

    const int aRow = lane & 15;
    const int aK   = (lane >> 4) * 8;
    const int bRow = (lane & 7) + ((lane >> 4) & 1) * 8;
    const int bK   = ((lane >> 3) & 1) * 8;

    float acc[4][4][4];
#pragma unroll
    for (int i = 0; i < 4; i++)
#pragma unroll
        for (int j = 0; j < 4; j++)
#pragma unroll
            for (int q = 0; q < 4; q++) acc[i][j][q] = 0.f;

    // ---- Phase A1: S = Q·K^T, 3-pass, k = 128 (8 steps) ----
    {
        const uint32_t aA = sb + ASM_QH, lA = sb + ASM_QL;
        const uint32_t aB = sb + ASM_KH, lB = sb + ASM_KL;
#pragma unroll
        for (int s = 0; s < 8; s++) {
            uint32_t bhf[2][4], blf[2][4];
#pragma unroll
            for (int p = 0; p < 2; p++) {
                uint32_t off = (uint32_t)((wn + p * 16 + bRow) * APAD + s * 16 + bK) * 2;
                ldmx4(bhf[p], aB + off);
                ldmx4(blf[p], lB + off);
            }
#pragma unroll
            for (int am = 0; am < 4; am++) {
                uint32_t off = (uint32_t)((wm + am * 16 + aRow) * APAD + s * 16 + aK) * 2;
                uint32_t ah[4], al[4];
                ldmx4(ah, aA + off);
                ldmx4(al, lA + off);
#pragma unroll
                for (int an = 0; an < 4; an++) {
                    const uint32_t* bhp = &bhf[an >> 1][(an & 1) * 2];
                    const uint32_t* blp = &blf[an >> 1][(an & 1) * 2];
                    mma16816(acc[am][an], ah, bhp);
                    mma16816(acc[am][an], ah, blp);
                    mma16816(acc[am][an], al, bhp);
                }
            }
        }
    }
#pragma unroll
    for (int am = 0; am < 4; am++)
#pragma unroll
        for (int an = 0; an < 4; an++) {
            int row = wm + am * 16 + (lane >> 2);
            int col = wn + an * 8 + (lane & 3) * 2;
            Ss[row * SP2 + col]           = acc[am][an][0];
            Ss[row * SP2 + col + 1]       = acc[am][an][1];
            Ss[(row + 8) * SP2 + col]     = acc[am][an][2];
            Ss[(row + 8) * SP2 + col + 1] = acc[am][an][3];
        }
    __syncthreads();

    // ---- Phase B: softmax (warp per row) ----
    {
        for (int r = wid; r < 128; r += 8) {
            float v[4];
            float mx = -INFINITY;
#pragma unroll
            for (int u = 0; u < 4; u++) {
                int c = u * 32 + lane;
                float s = Ss[r * SP2 + c];
                s = (msk[c] != 0.f) ? -1e10f : s * INV_SCALE;
                v[u] = s;
                mx = fmaxf(mx, s);
            }
#pragma unroll
            for (int o = 16; o; o >>= 1) mx = fmaxf(mx, __shfl_xor_sync(0xffffffffu, mx, o));
            float sum = 0.f;
#pragma unroll
            for (int u = 0; u < 4; u++) { v[u] = expf(v[u] - mx); sum += v[u]; }
#pragma unroll
            for (int o = 16; o; o >>= 1) sum += __shfl_xor_sync(0xffffffffu, sum, o);
            float inv = 1.f / sum;
#pragma unroll
            for (int u = 0; u < 4; u++) Ss[r * SP2 + u * 32 + lane] = v[u] * inv;
        }
    }
    __syncthreads();

    // ---- Phase C: P -> hi/lo (Q region); V -> transposed hi/lo (K region) ----
    {
        __nv_bfloat16* Ph = (__nv_bfloat16*)(smem + ASM_QH);
        __nv_bfloat16* Pl = (__nv_bfloat16*)(smem + ASM_QL);
#pragma unroll
        for (int i = 0; i < 32; i++) {
            int idx = tid + i * 256;          // 8192 u32 jobs
            int row = idx >> 6, c2 = idx & 63;
            float v0 = Ss[row * SP2 + c2 * 2];
            float v1 = Ss[row * SP2 + c2 * 2 + 1];
            __nv_bfloat16 h0 = __float2bfloat16(v0), h1 = __float2bfloat16(v1);
            int so = row * APAD + c2 * 2;     // c2*2 <= 126 < 136
            *(uint32_t*)&Ph[so] = pack_bf2(h0, h1);
            *(uint32_t*)&Pl[so] = pack_bf2(
                __float2bfloat16(v0 - __bfloat162float(h0)),
                __float2bfloat16(v1 - __bfloat162float(h1)));
        }
        __nv_bfloat16* Vth = (__nv_bfloat16*)(smem + ASM_KH);
        __nv_bfloat16* Vtl = (__nv_bfloat16*)(smem + ASM_KL);
#pragma unroll
        for (int i = 0; i < 16; i++) {
            int idx = tid + i * 256;          // 4096 float4 jobs
            int n = idx >> 5, d4 = idx & 31;
            float4 v = *(const float4*)&vh[rowbase + (size_t)n * 256 + d4 * 4];
            float vv[4] = {v.x, v.y, v.z, v.w};
#pragma unroll
            for (int j = 0; j < 4; j++) {
                int d = d4 * 4 + j;
                __nv_bfloat16 hh = __float2bfloat16(vv[j]);
                Vth[d * APAD + n] = hh;       // n <= 127 < 136
                Vtl[d * APAD + n] = __float2bfloat16(vv[j] - __bfloat162float(hh));
            }
        }
    }
    __syncthreads();

    // ---- Phase D: O = P·V, 3-pass ----
#pragma unroll
    for (int i = 0; i < 4; i++)
#pragma unroll
        for (int j = 0; j < 4; j++)
#pragma unroll
            for (int q = 0; q < 4; q++) acc[i][j][q] = 0.f;
    {
        const uint32_t aA = sb + ASM_QH, lA = sb + ASM_QL;
        const uint32_t aB = sb + ASM_KH, lB = sb + ASM_KL;
#pragma unroll
        for (int s = 0; s < 8; s++) {
            uint32_t bhf[2][4], blf[2][4];
#pragma unroll
            for (int p = 0; p < 2; p++) {
                uint32_t off = (uint32_t)((wn + p * 16 + bRow) * APAD + s * 16 + bK) * 2;
                ldmx4(bhf[p], aB + off);
                ldmx4(blf[p], lB + off);
            }
#pragma unroll
            for (int am = 0; am < 4; am++) {
                uint32_t off = (uint32_t)((wm + am * 16 + aRow) * APAD + s * 16 + aK) * 2;
                uint32_t ah[4], al[4];
                ldmx4(ah, aA + off);
                ldmx4(al, lA + off);
#pragma unroll
                for (int an = 0; an < 4; an++) {
                    const uint32_t* bhp = &bhf[an >> 1][(an & 1) * 2];
                    const uint32_t* blp = &blf[an >> 1][(an & 1) * 2];
                    mma16816(acc[am][an], ah, bhp);
                    mma16816(acc[am][an], ah, blp);
                    mma16816(acc[am][an], al, bhp);
                }
            }
        }
    }

    // ---- epilogue: write ao hi/lo ----
#pragma unroll
    for (int am = 0; am < 4; am++)
#pragma unroll
        for (int an = 0; an < 4; an++) {
            int row = wm + am * 16 + (lane >> 2);
            int col = wn + an * 8 + (lane & 3) * 2;
            float v0 = acc[am][an][0], v1 = acc[am][an][1];
            float v2 = acc[am][an][2], v3 = acc[am][an][3];
            __nv_bfloat16 h0 = __float2bfloat16(v0), h1 = __float2bfloat16(v1);
            __nv_bfloat16 h2 = __float2bfloat16(v2), h3 = __float2bfloat16(v3);
            size_t o0 = rowbase + (size_t)row * 256 + col;
            size_t o1 = rowbase + (size_t)(row + 8) * 256 + col;
            *(uint32_t*)&aoh[o0] = pack_bf2(h0, h1);
            *(uint32_t*)&aol[o0] = pack_bf2(
                __float2bfloat16(v0 - __bfloat162float(h0)),
                __float2bfloat16(v1 - __bfloat162float(h1)));
            *(uint32_t*)&aoh[o1] = pack_bf2(h2, h3);
            *(uint32_t*)&aol[o1] = pack_bf2(
                __float2bfloat16(v2 - __bfloat162float(h2)),
                __float2bfloat16(v3 - __bfloat162float(h3)));
        }
}

// ---------------------------------------------------------------------------
// SA epilogue LN -> bf16 hi/lo output
// ---------------------------------------------------------------------------
__launch_bounds__(256)
__global__ void sa_ln_kernel(const float* __restrict__ tmp,
                             const float* __restrict__ fcb,
                             const float* __restrict__ seq,
                             const float* __restrict__ seq_t,
                             const float* __restrict__ lng,
                             const float* __restrict__ lnb,
                             __nv_bfloat16* __restrict__ sah,
                             __nv_bfloat16* __restrict__ sal) {
    const int warp = threadIdx.x >> 5, lane = threadIdx.x & 31;
    const size_t row = (size_t)blockIdx.x * 8 + warp;
    float v[8];
#pragma unroll
    for (int u = 0; u < 8; u++) {
        int c = u*32 + lane;
        float res = (c < 128) ? seq[row*128 + c] : seq_t[row*128 + (c-128)];
        v[u] = tmp[row*256 + c] + fcb[c] + res;
    }
    float s = 0.f;
#pragma unroll
    for (int u = 0; u < 8; u++) s += v[u];
#pragma unroll
    for (int o = 16; o; o >>= 1) s += __shfl_xor_sync(0xffffffffu, s, o);
    float m = s * (1.f/256.f);
    float q = 0.f;
#pragma unroll
    for (int u = 0; u < 8; u++) { float d = v[u] - m; q += d*d; }
#pragma unroll
    for (int o = 16; o; o >>= 1) q += __shfl_xor_sync(0xffffffffu, q, o);
    float inv = rsqrtf(q * (1.f/256.f) + LN_EPS);
#pragma unroll
    for (int u = 0; u < 8; u++) {
        int c = u*32 + lane;
        float y = (v[u] - m) * inv * lng[c] + lnb[c];
        __nv_bfloat16 hh = __float2bfloat16(y);
        sah[row*256 + c] = hh;
        sal[row*256 + c] = __float2bfloat16(y - __bfloat162float(hh));
    }
}

// ---------------------------------------------------------------------------
// Cross-attention
// ---------------------------------------------------------------------------
__launch_bounds__(256)
__global__ void ca_attn_kernel(const float* __restrict__ cq,
                               const float* __restrict__ ckh,
                               const float* __restrict__ cvh,
                               const void*  __restrict__ mask,
                               float* __restrict__ cao,
                               float* __restrict__ attn_out) {
    __shared__ float qs[256];
    __shared__ float sc[256];
    __shared__ float mred[2], sred[2];
    __shared__ float msk[128];
    const int b = blockIdx.x, t = threadIdx.x;

    qs[t] = cq[(size_t)b*256 + t];
    if (t < 128) msk[t] = is_masked(mask, b*128 + t) ? 1.f : 0.f;
    __syncthreads();

    const int h = t >> 7, n = t & 127;
    {
        const float4* k4 = (const float4*)(ckh + ((size_t)(b*128 + n))*256 + h*128);
        const float4* q4 = (const float4*)&qs[h*128];
        float s = 0.f;
#pragma unroll 8
        for (int k = 0; k < 32; k++) {
            float4 kv = k4[k], qv = q4[k];
            s += qv.x*kv.x + qv.y*kv.y + qv.z*kv.z + qv.w*kv.w;
        }
        s = (msk[n] != 0.f) ? -1e10f : s * INV_SCALE;
        sc[t] = s;
    }
    __syncthreads();

    const int warp = t >> 5, lane = t & 31;
    if (warp < 2) {
        float v[4]; float mx = -INFINITY;
#pragma unroll
        for (int u = 0; u < 4; u++) { v[u] = sc[warp*128 + u*32 + lane]; mx = fmaxf(mx, v[u]); }
#pragma unroll
        for (int o = 16; o; o >>= 1) mx = fmaxf(mx, __shfl_xor_sync(0xffffffffu, mx, o));
        float sum = 0.f;
#pragma unroll
        for (int u = 0; u < 4; u++) sum += expf(v[u] - mx);
#pragma unroll
        for (int o = 16; o; o >>= 1) sum += __shfl_xor_sync(0xffffffffu, sum, o);
        if (lane == 0) { mred[warp] = mx; sred[warp] = sum; }
    }
    __syncthreads();

    float p = expf(sc[t] - mred[h]) / sred[h];
    sc[t] = p;
    attn_out[((size_t)(h*BATCH + b))*128 + n] = p;
    __syncthreads();

    float acc = 0.f;
    const int hh = t >> 7;
    for (int nn = 0; nn < 128; nn++)
        acc = fmaf(sc[hh*128 + nn], cvh[((size_t)(b*128 + nn))*256 + t], acc);
    cao[(size_t)b*256 + t] = acc;
}

// ---------------------------------------------------------------------------
// CA epilogue fc+LN
// ---------------------------------------------------------------------------
__launch_bounds__(256)
__global__ void ca_fc_ln_kernel(const float* __restrict__ cao,
                                const float* __restrict__ fcw,
                                const float* __restrict__ fcb,
                                const float* __restrict__ src,
                                const float* __restrict__ src_t,
                                const float* __restrict__ lng,
                                const float* __restrict__ lnb,
                                float* __restrict__ caout) {
    __shared__ float x[256];
    __shared__ float rbuf[8];
    __shared__ float stat[2];
    const int b = blockIdx.x, t = threadIdx.x;
    x[t] = cao[(size_t)b*256 + t];
    __syncthreads();

    float res = (t < 128) ? src[(size_t)b*128 + t] : src_t[(size_t)b*128 + (t-128)];
    float acc = fcb[t] + res;
    for (int k = 0; k < 256; k++)
        acc = fmaf(x[k], fcw[(size_t)k*256 + t], acc);

    float s = acc;
#pragma unroll
    for (int o = 16; o; o >>= 1) s += __shfl_xor_sync(0xffffffffu, s, o);
    if ((t & 31) == 0) rbuf[t >> 5] = s;
    __syncthreads();
    if (t == 0) {
        float tot = 0.f;
        for (int i = 0; i < 8; i++) tot += rbuf[i];
        stat[0] = tot * (1.f/256.f);
    }
    __syncthreads();
    float m = stat[0];
    float d = acc - m;
    float q = d*d;
#pragma unroll
    for (int o = 16; o; o >>= 1) q += __shfl_xor_sync(0xffffffffu, q, o);
    __syncthreads();
    if ((t & 31) == 0) rbuf[t >> 5] = q;
    __syncthreads();
    if (t == 0) {
        float tot = 0.f;
        for (int i = 0; i < 8; i++) tot += rbuf[i];
        stat[1] = rsqrtf(tot * (1.f/256.f) + LN_EPS);
    }
    __syncthreads();
    caout[(size_t)b*256 + t] = d * stat[1] * lng[t] + lnb[t];
}

// ---------------------------------------------------------------------------
// Final MLP
// ---------------------------------------------------------------------------
__launch_bounds__(128)
__global__ void mg_kernel(const float* __restrict__ caout,
                          const float* __restrict__ src,
                          const float* __restrict__ w1, const float* __restrict__ b1,
                          const float* __restrict__ w2, const float* __restrict__ b2,
                          float* __restrict__ out) {
    __shared__ float x[384];
    __shared__ float h1[128];
    const int b = blockIdx.x, t = threadIdx.x;
    x[t]       = caout[(size_t)b*256 + t];
    x[128 + t] = caout[(size_t)b*256 + 128 + t];
    x[256 + t] = src[(size_t)b*128 + t];
    __syncthreads();
    float acc = b1[t];
    for (int k = 0; k < 384; k++)
        acc = fmaf(x[k], w1[(size_t)k*128 + t], acc);
    h1[t] = fmaxf(acc, 0.f);
    __syncthreads();
    float o = b2[t];
    for (int k = 0; k < 128; k++)
        o = fmaf(h1[k], w2[(size_t)k*128 + t], o);
    out[(size_t)b*128 + t] = o;
}

// ---------------------------------------------------------------------------
// Launch
// ---------------------------------------------------------------------------
extern "C" void kernel_launch(void* const* d_in, const int* in_sizes, int n_in,
                              void* d_out, int out_size) {
    const float *src, *src_t, *seq, *seq_t;
    const void  *mask;
    const float *sa_wq, *sa_wk, *sa_wv, *sa_fcw, *sa_fcb, *sa_lng, *sa_lnb;
    const float *ms_w1, *ms_b1, *ms_w2, *ms_b2;
    const float *ca_wq, *ca_wk, *ca_wv, *ca_fcw, *ca_fcb, *ca_lng, *ca_lnb;
    const float *mg_w1, *mg_b1, *mg_w2, *mg_b2;

#define F(i) ((const float*)d_in[(i)])
    src = F(0); src_t = F(1); seq = F(2); seq_t = F(3); mask = d_in[4];
    if (in_sizes[10] == 98304) {
        sa_wq = F(5); sa_wk = F(6); sa_wv = F(7); sa_fcw = F(8); sa_fcb = F(9);
        ms_w1 = F(10); ms_b1 = F(11); ms_w2 = F(12); ms_b2 = F(13);
        ca_wq = F(14); ca_wk = F(15); ca_wv = F(16); ca_fcw = F(17); ca_fcb = F(18);
        mg_w1 = F(19); mg_b1 = F(20); mg_w2 = F(21); mg_b2 = F(22);
        sa_lng = F(23); sa_lnb = F(24); ca_lng = F(25); ca_lnb = F(26);
    } else {
        sa_wq = F(5); sa_wk = F(6); sa_wv = F(7); sa_fcw = F(8); sa_fcb = F(9);
        sa_lng = F(10); sa_lnb = F(11);
        ms_w1 = F(12); ms_b1 = F(13); ms_w2 = F(14); ms_b2 = F(15);
        ca_wq = F(16); ca_wk = F(17); ca_wv = F(18); ca_fcw = F(19); ca_fcb = F(20);
        ca_lng = F(21); ca_lnb = F(22);
        mg_w1 = F(23); mg_b1 = F(24); mg_w2 = F(25); mg_b2 = F(26);
    }
#undef F

    float* out      = (float*)d_out;
    float* attn_out = out + BATCH*FEAT;

    float *qh,*kh,*vh,*tmp,*ckh,*cvh,*cq,*cao,*cln;
    __nv_bfloat16 *whi,*wlo,*seqh,*seql,*aoh,*aol,*sah,*sal,*h1h,*h1l,*k2h,*k2l,*srch,*srcl;
    cudaGetSymbolAddress((void**)&qh,  g_qh);
    cudaGetSymbolAddress((void**)&kh,  g_kh);
    cudaGetSymbolAddress((void**)&vh,  g_vh);
    cudaGetSymbolAddress((void**)&tmp, g_tmp);
    cudaGetSymbolAddress((void**)&ckh, g_ckh);
    cudaGetSymbolAddress((void**)&cvh, g_cvh);
    cudaGetSymbolAddress((void**)&cq,  g_cq);
    cudaGetSymbolAddress((void**)&cao, g_cao);
    cudaGetSymbolAddress((void**)&cln, g_cln);
    cudaGetSymbolAddress((void**)&whi, g_whi);
    cudaGetSymbolAddress((void**)&wlo, g_wlo);
    cudaGetSymbolAddress((void**)&seqh, g_seqh);
    cudaGetSymbolAddress((void**)&seql, g_seql);
    cudaGetSymbolAddress((void**)&aoh, g_aoh);
    cudaGetSymbolAddress((void**)&aol, g_aol);
    cudaGetSymbolAddress((void**)&sah, g_sah);
    cudaGetSymbolAddress((void**)&sal, g_sal);
    cudaGetSymbolAddress((void**)&h1h, g_h1h);
    cudaGetSymbolAddress((void**)&h1l, g_h1l);
    cudaGetSymbolAddress((void**)&k2h, g_k2h);
    cudaGetSymbolAddress((void**)&k2l, g_k2l);
    cudaGetSymbolAddress((void**)&srch, g_srch);
    cudaGetSymbolAddress((void**)&srcl, g_srcl);

    cudaFuncSetAttribute(sa_attn_kernel,
                         cudaFuncAttributeMaxDynamicSharedMemorySize, SA_SMEM_BYTES);
    cudaFuncSetAttribute(hmma_gemm_kernel<0,0>,
                         cudaFuncAttributeMaxDynamicSharedMemorySize, GEMM_SMEM);
    cudaFuncSetAttribute(hmma_gemm_kernel<2,1>,
                         cudaFuncAttributeMaxDynamicSharedMemorySize, GEMM_SMEM);
    cudaFuncSetAttribute(hmma_gemm_kernel<1,1>,
                         cudaFuncAttributeMaxDynamicSharedMemorySize, GEMM_SMEM);

    detect_mask_kernel<<<1, 256>>>(mask);

    // activation splits
    split_concat_kernel<<<ROWS/4, 256>>>(seq, seq_t, seqh, seql);
    split_concat_kernel<<<BATCH/4, 256>>>(src, src_t, srch, srcl);

    // weight prep
    const dim3 wb(32, 8);
    wsplit_kernel<<<dim3(8,  8), wb>>>(sa_wq,  256, 256, whi+WOFF_SAWQ,  wlo+WOFF_SAWQ);
    wsplit_kernel<<<dim3(8,  8), wb>>>(sa_wk,  256, 256, whi+WOFF_SAWK,  wlo+WOFF_SAWK);
    wsplit_kernel<<<dim3(8,  8), wb>>>(sa_wv,  256, 256, whi+WOFF_SAWV,  wlo+WOFF_SAWV);
    wsplit_kernel<<<dim3(8,  8), wb>>>(sa_fcw, 256, 256, whi+WOFF_SAFCW, wlo+WOFF_SAFCW);
    wsplit_kernel<<<dim3(8, 12), wb>>>(ms_w1,  384, 256, whi+WOFF_MSW1,  wlo+WOFF_MSW1);
    wsplit_kernel<<<dim3(8,  8), wb>>>(ms_w2,  256, 256, whi+WOFF_MSW2,  wlo+WOFF_MSW2);
    wsplit_kernel<<<dim3(8,  8), wb>>>(ca_wq,  256, 256, whi+WOFF_CAWQ,  wlo+WOFF_CAWQ);
    wsplit_kernel<<<dim3(8,  8), wb>>>(ca_wk,  256, 256, whi+WOFF_CAWK,  wlo+WOFF_CAWK);
    wsplit_kernel<<<dim3(8,  8), wb>>>(ca_wv,  256, 256, whi+WOFF_CAWV,  wlo+WOFF_CAWV);

    // 1. fused QKV (N=768)
    hmma_gemm_kernel<0,0><<<dim3(6, ROWS/128), 256, GEMM_SMEM>>>(
        seqh, seql, 256, 256, nullptr, nullptr, 0, 0,
        whi+WOFF_SAWQ, wlo+WOFF_SAWQ, nullptr, qh, kh, vh, nullptr, nullptr);

    // 2. SA attention (HMMA) -> ao split
    sa_attn_kernel<<<BATCH*NHEAD, 256, SA_SMEM_BYTES>>>(qh, kh, vh, mask, aoh, aol);

    // 3. SA fc
    hmma_gemm_kernel<0,0><<<dim3(2, ROWS/128), 256, GEMM_SMEM>>>(
        aoh, aol, 256, 256, nullptr, nullptr, 0, 0,
        whi+WOFF_SAFCW, wlo+WOFF_SAFCW, nullptr, tmp, nullptr, nullptr, nullptr, nullptr);

    // 4. bias+residual+LN -> sa split
    sa_ln_kernel<<<ROWS/8, 256>>>(tmp, sa_fcb, seq, seq_t, sa_lng, sa_lnb, sah, sal);

    // 5. MLP1 (K=384) -> h1 split
    hmma_gemm_kernel<2,1><<<dim3(2, ROWS/128), 256, GEMM_SMEM>>>(
        sah, sal, 256, 256, seqh, seql, 128, 256,
        whi+WOFF_MSW1, wlo+WOFF_MSW1, ms_b1, nullptr, nullptr, nullptr, h1h, h1l);

    // 6. MLP2 -> k2 split
    hmma_gemm_kernel<1,1><<<dim3(2, ROWS/128), 256, GEMM_SMEM>>>(
        h1h, h1l, 256, 256, nullptr, nullptr, 0, 0,
        whi+WOFF_MSW2, wlo+WOFF_MSW2, ms_b2, nullptr, nullptr, nullptr, k2h, k2l);

    // 7. fused CA K/V (N=512)
    hmma_gemm_kernel<0,0><<<dim3(4, ROWS/128), 256, GEMM_SMEM>>>(
        k2h, k2l, 256, 256, nullptr, nullptr, 0, 0,
        whi+WOFF_CAWK, wlo+WOFF_CAWK, nullptr, ckh, cvh, nullptr, nullptr, nullptr);

    // 8. CA Q
    hmma_gemm_kernel<0,0><<<dim3(2, BATCH/128), 256, GEMM_SMEM>>>(
        srch, srcl, 256, 256, nullptr, nullptr, 0, 0,
        whi+WOFF_CAWQ, wlo+WOFF_CAWQ, nullptr, cq, nullptr, nullptr, nullptr, nullptr);

    // 9. CA attention (writes attn part of d_out)
    ca_attn_kernel<<<BATCH, 256>>>(cq, ckh, cvh, mask, cao, attn_out);

    // 10. CA fc + residual + LN
    ca_fc_ln_kernel<<<BATCH, 256>>>(cao, ca_fcw, ca_fcb, src, src_t, ca_lng, ca_lnb, cln);

    // 11. Final MLP -> out part of d_out
    mg_kernel<<<BATCH, 128>>>(cln, src, mg_w1, mg_b1, mg_w2, mg_b2, out);
}